// round 6
// baseline (speedup 1.0000x reference)
#include <cuda_runtime.h>
#include <cuda_bf16.h>
#include <cstdint>

// ScaledDotProductAttention B=4,H=16,S=2048,D=64 fp32 + mask [B,1,S,S] int32.
// out [B,H,S,D] then weights [B,H,S,S] concatenated in d_out.
//
// Round 5: two-kernel split with e staged in the W output region.
//   k1 (sdpa_qk): QK 3-split bf16 MMA + mask + exp -> raw e to W, rowsums -> g_rsum.
//   k2 (sdpa_pv): read e from W in A-frag layout, write W*rinv back, PV MMA -> O.
// QK computed once, exp once, mask read once; PV pass has no K traffic.

#define B_ 4
#define H_ 16
#define S_ 2048
#define D_ 64

constexpr int BM = 128, BN = 128, NT = 256, NTILE = S_ / BN;
constexpr int RB = 144;                    // bytes per bf16 smem row (72 elems)

// k1 smem: Q (then K) hi/lo
constexpr int OFF_KH = 0;
constexpr int OFF_KL = OFF_KH + BM * RB;   // 18432
constexpr int SMEM_1 = OFF_KL + BM * RB;   // 36864
// k2 smem: V hi/lo + rinv
constexpr int OFF_VH   = 0;
constexpr int OFF_VL   = OFF_VH + BM * RB;     // 18432
constexpr int OFF_RINV = OFF_VL + BM * RB;     // 36864
constexpr int SMEM_2   = OFF_RINV + 512;       // 37376

__device__ float g_rsum[B_ * H_ * S_];

// ---------- helpers ----------
__device__ __forceinline__ uint32_t smem_u32(const void* p) {
    uint32_t a;
    asm("{ .reg .u64 t; cvta.to.shared.u64 t, %1; cvt.u32.u64 %0, t; }" : "=r"(a) : "l"(p));
    return a;
}
__device__ __forceinline__ void ldsm4(uint32_t* r, uint32_t a) {
    asm volatile("ldmatrix.sync.aligned.m8n8.x4.shared.b16 {%0,%1,%2,%3}, [%4];"
                 : "=r"(r[0]), "=r"(r[1]), "=r"(r[2]), "=r"(r[3]) : "r"(a));
}
__device__ __forceinline__ void ldsm4t(uint32_t* r, uint32_t a) {
    asm volatile("ldmatrix.sync.aligned.m8n8.x4.trans.shared.b16 {%0,%1,%2,%3}, [%4];"
                 : "=r"(r[0]), "=r"(r[1]), "=r"(r[2]), "=r"(r[3]) : "r"(a));
}
__device__ __forceinline__ void mma_bf16(float* c, const uint32_t* a, uint32_t b0, uint32_t b1) {
    asm volatile(
        "mma.sync.aligned.m16n8k16.row.col.f32.bf16.bf16.f32 "
        "{%0,%1,%2,%3}, {%4,%5,%6,%7}, {%8,%9}, {%0,%1,%2,%3};"
        : "+f"(c[0]), "+f"(c[1]), "+f"(c[2]), "+f"(c[3])
        : "r"(a[0]), "r"(a[1]), "r"(a[2]), "r"(a[3]), "r"(b0), "r"(b1));
}
__device__ __forceinline__ void split2pack(float a, float b, uint32_t& hp, uint32_t& lp) {
    __nv_bfloat162 h = __floats2bfloat162_rn(a, b);
    float2 hf = __bfloat1622float2(h);
    __nv_bfloat162 l = __floats2bfloat162_rn(a - hf.x, b - hf.y);
    hp = *(uint32_t*)&h;
    lp = *(uint32_t*)&l;
}
__device__ __forceinline__ void load_split(const float* __restrict__ g, char* smH, char* smL,
                                           float scale, int tid) {
    for (int idx = tid; idx < BM * 16; idx += NT) {
        int r = idx >> 4, c4 = (idx & 15) * 4;
        float4 v = *(const float4*)(g + (size_t)r * D_ + c4);
        v.x *= scale; v.y *= scale; v.z *= scale; v.w *= scale;
        uint32_t h0, l0, h1, l1;
        split2pack(v.x, v.y, h0, l0);
        split2pack(v.z, v.w, h1, l1);
        *(uint2*)(smH + r * RB + c4 * 2) = make_uint2(h0, h1);
        *(uint2*)(smL + r * RB + c4 * 2) = make_uint2(l0, l1);
    }
}

// scores for one 16m x 64n chunk (3-split bf16), Q frags in regs
__device__ __forceinline__ void qk_chunk(uint32_t sb, int co, int mi, int l7,
                                         const uint32_t aQH[4][4], const uint32_t aQL[4][4],
                                         float c[8][4]) {
    #pragma unroll
    for (int nf = 0; nf < 8; ++nf)
        #pragma unroll
        for (int i = 0; i < 4; ++i) c[nf][i] = 0.f;

    #pragma unroll
    for (int kc = 0; kc < 4; ++kc) {
        const uint32_t bcol = kc * 32 + (mi & 1) * 16;
        #pragma unroll
        for (int nf2 = 0; nf2 < 4; ++nf2) {
            uint32_t bH[4], bL[4];
            uint32_t brow = (uint32_t)(co + nf2 * 16 + ((mi >> 1) << 3) + l7) * RB;
            ldsm4(bH, sb + OFF_KH + brow + bcol);
            ldsm4(bL, sb + OFF_KL + brow + bcol);
            mma_bf16(c[2 * nf2],     aQH[kc], bH[0], bH[1]);
            mma_bf16(c[2 * nf2 + 1], aQH[kc], bH[2], bH[3]);
            mma_bf16(c[2 * nf2],     aQH[kc], bL[0], bL[1]);
            mma_bf16(c[2 * nf2 + 1], aQH[kc], bL[2], bL[3]);
            mma_bf16(c[2 * nf2],     aQL[kc], bH[0], bH[1]);
            mma_bf16(c[2 * nf2 + 1], aQL[kc], bH[2], bH[3]);
        }
    }
}

// ---------- k1: QK + exp -> raw e in W + rowsums ----------
__global__ void __launch_bounds__(NT, 2)
sdpa_qk(const float* __restrict__ Q, const float* __restrict__ K,
        const int* __restrict__ mask, float* __restrict__ wts)
{
    extern __shared__ char sm[];
    const uint32_t sb = smem_u32(sm);
    const int tid = threadIdx.x, w = tid >> 5, lid = tid & 31;
    const int g = lid >> 2, tl = lid & 3, mi = lid >> 3, l7 = lid & 7;
    const int bh = blockIdx.y, b = bh >> 4, q0 = blockIdx.x * BM;

    const float* Qg = Q + ((size_t)bh * S_ + q0) * D_;
    const float* Kg = K + (size_t)bh * S_ * D_;
    const int*   Mg = mask + (size_t)b * S_ * S_;
    float*       Wg = wts + ((size_t)bh * S_ + q0) * S_;

    load_split(Qg, sm + OFF_KH, sm + OFF_KL, 0.125f, tid);
    __syncthreads();

    uint32_t aQH[4][4], aQL[4][4];
    {
        uint32_t arow = (uint32_t)(16 * w + ((mi & 1) << 3) + l7) * RB;
        #pragma unroll
        for (int kc = 0; kc < 4; ++kc) {
            uint32_t acol = kc * 32 + (mi >> 1) * 16;
            ldsm4(aQH[kc], sb + OFF_KH + arow + acol);
            ldsm4(aQL[kc], sb + OFF_KL + arow + acol);
        }
    }

    const int r0 = 16 * w + g;
    const int* m0p = Mg + (size_t)(q0 + r0) * S_;
    const int* m1p = Mg + (size_t)(q0 + r0 + 8) * S_;
    float* w0p = Wg + (size_t)r0 * S_;
    float* w1p = Wg + (size_t)(r0 + 8) * S_;
    float rs0 = 0.f, rs1 = 0.f;

    for (int t = 0; t < NTILE; ++t) {
        __syncthreads();
        load_split(Kg + (size_t)t * BN * D_, sm + OFF_KH, sm + OFF_KL, 1.f, tid);
        __syncthreads();

        #pragma unroll
        for (int ch2 = 0; ch2 < 2; ++ch2) {
            const int co = 64 * ch2;
            float c[8][4];
            qk_chunk(sb, co, mi, l7, aQH, aQL, c);
            const int colb = t * BN + co;
            #pragma unroll
            for (int nf = 0; nf < 8; ++nf) {
                int col = colb + 8 * nf + 2 * tl;
                int2 mA = *(const int2*)(m0p + col);
                int2 mB = *(const int2*)(m1p + col);
                float e0 = mA.x ? __expf(c[nf][0]) : 0.f;
                float e1 = mA.y ? __expf(c[nf][1]) : 0.f;
                float e2 = mB.x ? __expf(c[nf][2]) : 0.f;
                float e3 = mB.y ? __expf(c[nf][3]) : 0.f;
                *(float2*)(w0p + col) = make_float2(e0, e1);
                *(float2*)(w1p + col) = make_float2(e2, e3);
                rs0 += e0 + e1;
                rs1 += e2 + e3;
            }
        }
    }

    rs0 += __shfl_xor_sync(0xffffffffu, rs0, 1);
    rs0 += __shfl_xor_sync(0xffffffffu, rs0, 2);
    rs1 += __shfl_xor_sync(0xffffffffu, rs1, 1);
    rs1 += __shfl_xor_sync(0xffffffffu, rs1, 2);
    if (tl == 0) {
        g_rsum[(size_t)bh * S_ + q0 + r0]     = rs0;
        g_rsum[(size_t)bh * S_ + q0 + r0 + 8] = rs1;
    }
}

// ---------- k2: read e from W, normalize W, PV -> O ----------
__global__ void __launch_bounds__(NT, 3)
sdpa_pv(const float* __restrict__ V, float* __restrict__ out,
        float* __restrict__ wts)
{
    extern __shared__ char sm[];
    const uint32_t sb = smem_u32(sm);
    const int tid = threadIdx.x, w = tid >> 5, lid = tid & 31;
    const int g = lid >> 2, tl = lid & 3, mi = lid >> 3, l7 = lid & 7;
    const int bh = blockIdx.y, q0 = blockIdx.x * BM;

    const float* Vg = V + (size_t)bh * S_ * D_;
    float*       Wg = wts + ((size_t)bh * S_ + q0) * S_;
    float*       Og = out + ((size_t)bh * S_ + q0) * D_;

    float* rinv = (float*)(sm + OFF_RINV);
    if (tid < 128)
        rinv[tid] = 1.0f / g_rsum[(size_t)bh * S_ + q0 + tid];
    __syncthreads();

    const int r0 = 16 * w + g;
    const float ri0 = rinv[r0], ri1 = rinv[r0 + 8];
    float* w0p = Wg + (size_t)r0 * S_;
    float* w1p = Wg + (size_t)(r0 + 8) * S_;

    float o[8][4];
    #pragma unroll
    for (int df = 0; df < 8; ++df)
        #pragma unroll
        for (int i = 0; i < 4; ++i) o[df][i] = 0.f;

    for (int t = 0; t < NTILE; ++t) {
        __syncthreads();
        load_split(Vg + (size_t)t * BN * D_, sm + OFF_VH, sm + OFF_VL, 1.f, tid);
        __syncthreads();

        #pragma unroll
        for (int ch2 = 0; ch2 < 2; ++ch2) {
            const int co = 64 * ch2;
            const int colb = t * BN + co;
            #pragma unroll
            for (int kc = 0; kc < 4; ++kc) {
                const int cb = colb + 16 * kc + 2 * tl;
                // e in A-fragment layout (each element read exactly once)
                float2 e00 = *(const float2*)(w0p + cb);
                float2 e10 = *(const float2*)(w1p + cb);
                float2 e01 = *(const float2*)(w0p + cb + 8);
                float2 e11 = *(const float2*)(w1p + cb + 8);
                // normalized W write-back
                *(float2*)(w0p + cb)     = make_float2(e00.x * ri0, e00.y * ri0);
                *(float2*)(w1p + cb)     = make_float2(e10.x * ri1, e10.y * ri1);
                *(float2*)(w0p + cb + 8) = make_float2(e01.x * ri0, e01.y * ri0);
                *(float2*)(w1p + cb + 8) = make_float2(e11.x * ri1, e11.y * ri1);
                // pack P A-frags (hi/lo)
                uint32_t ah[4], al[4];
                split2pack(e00.x, e00.y, ah[0], al[0]);
                split2pack(e10.x, e10.y, ah[1], al[1]);
                split2pack(e01.x, e01.y, ah[2], al[2]);
                split2pack(e11.x, e11.y, ah[3], al[3]);
                // PV for this k16 block (3-split)
                uint32_t vrow = (uint32_t)(co + kc * 16 + ((mi & 1) << 3) + l7) * RB;
                #pragma unroll
                for (int db2 = 0; db2 < 4; ++db2) {
                    uint32_t vh[4], vl[4];
                    uint32_t va = sb + OFF_VH + vrow + db2 * 32 + (mi >> 1) * 16;
                    ldsm4t(vh, va);
                    ldsm4t(vl, va + (OFF_VL - OFF_VH));
                    mma_bf16(o[2 * db2],     ah, vh[0], vh[1]);
                    mma_bf16(o[2 * db2 + 1], ah, vh[2], vh[3]);
                    mma_bf16(o[2 * db2],     ah, vl[0], vl[1]);
                    mma_bf16(o[2 * db2 + 1], ah, vl[2], vl[3]);
                    mma_bf16(o[2 * db2],     al, vh[0], vh[1]);
                    mma_bf16(o[2 * db2 + 1], al, vh[2], vh[3]);
                }
            }
        }
    }

    // epilogue: scale by rinv, store O
    #pragma unroll
    for (int df = 0; df < 8; ++df) {
        int colc = 8 * df + 2 * tl;
        *(float2*)(Og + (size_t)r0 * D_ + colc) =
            make_float2(o[df][0] * ri0, o[df][1] * ri0);
        *(float2*)(Og + (size_t)(r0 + 8) * D_ + colc) =
            make_float2(o[df][2] * ri1, o[df][3] * ri1);
    }
}

extern "C" void kernel_launch(void* const* d_in, const int* in_sizes, int n_in,
                              void* d_out, int out_size)
{
    const float* Q    = (const float*)d_in[0];
    const float* K    = (const float*)d_in[1];
    const float* V    = (const float*)d_in[2];
    const int*   mask = (const int*)d_in[3];

    float* out = (float*)d_out;
    float* wts = out + (size_t)B_ * H_ * S_ * D_;

    cudaFuncSetAttribute(sdpa_qk, cudaFuncAttributeMaxDynamicSharedMemorySize, SMEM_1);
    cudaFuncSetAttribute(sdpa_pv, cudaFuncAttributeMaxDynamicSharedMemorySize, SMEM_2);

    dim3 grid(S_ / BM, B_ * H_);
    sdpa_qk<<<grid, NT, SMEM_1>>>(Q, K, mask, wts);
    sdpa_pv<<<grid, NT, SMEM_2>>>(V, out, wts);
}

// round 7
// speedup vs baseline: 2.0518x; 2.0518x over previous
#include <cuda_runtime.h>
#include <cuda_bf16.h>
#include <cstdint>

// ScaledDotProductAttention B=4,H=16,S=2048,D=64 fp32 + mask [B,1,S,S] int32.
// out [B,H,S,D] then weights [B,H,S,S] concatenated in d_out.
//
// Round 6: single fused kernel (round-4 passB + in-kernel rowsums + in-place
// W rescale). QK 3-split bf16 HMMA, exp+mask once, raw e -> W, PV 3-split
// accumulates O in regs; epilogue: rinv, O write, W slab rescale (this CTA's
// rows only; __syncthreads gives block-scope global visibility).

#define B_ 4
#define H_ 16
#define S_ 2048
#define D_ 64

constexpr int BM = 128, BN = 128, NT = 256, NTILE = S_ / BN;
constexpr int RB = 144;                    // bytes per bf16 smem row (72 elems)

constexpr int OFF_KH   = 0;
constexpr int OFF_KL   = OFF_KH + BM * RB;     // 18432
constexpr int OFF_VH   = OFF_KL + BM * RB;     // 36864
constexpr int OFF_VL   = OFF_VH + BM * RB;     // 55296
constexpr int OFF_RINV = OFF_VL + BM * RB;     // 73728
constexpr int SMEM_SZ  = OFF_RINV + 512;       // 74240

// ---------- helpers ----------
__device__ __forceinline__ uint32_t smem_u32(const void* p) {
    uint32_t a;
    asm("{ .reg .u64 t; cvta.to.shared.u64 t, %1; cvt.u32.u64 %0, t; }" : "=r"(a) : "l"(p));
    return a;
}
__device__ __forceinline__ void ldsm4(uint32_t* r, uint32_t a) {
    asm volatile("ldmatrix.sync.aligned.m8n8.x4.shared.b16 {%0,%1,%2,%3}, [%4];"
                 : "=r"(r[0]), "=r"(r[1]), "=r"(r[2]), "=r"(r[3]) : "r"(a));
}
__device__ __forceinline__ void ldsm4t(uint32_t* r, uint32_t a) {
    asm volatile("ldmatrix.sync.aligned.m8n8.x4.trans.shared.b16 {%0,%1,%2,%3}, [%4];"
                 : "=r"(r[0]), "=r"(r[1]), "=r"(r[2]), "=r"(r[3]) : "r"(a));
}
__device__ __forceinline__ void mma_bf16(float* c, const uint32_t* a, uint32_t b0, uint32_t b1) {
    asm volatile(
        "mma.sync.aligned.m16n8k16.row.col.f32.bf16.bf16.f32 "
        "{%0,%1,%2,%3}, {%4,%5,%6,%7}, {%8,%9}, {%0,%1,%2,%3};"
        : "+f"(c[0]), "+f"(c[1]), "+f"(c[2]), "+f"(c[3])
        : "r"(a[0]), "r"(a[1]), "r"(a[2]), "r"(a[3]), "r"(b0), "r"(b1));
}
__device__ __forceinline__ void split2pack(float a, float b, uint32_t& hp, uint32_t& lp) {
    __nv_bfloat162 h = __floats2bfloat162_rn(a, b);
    float2 hf = __bfloat1622float2(h);
    __nv_bfloat162 l = __floats2bfloat162_rn(a - hf.x, b - hf.y);
    hp = *(uint32_t*)&h;
    lp = *(uint32_t*)&l;
}
template <bool SCALE>
__device__ __forceinline__ void load_split(const float* __restrict__ g, char* smH, char* smL,
                                           int tid) {
    for (int idx = tid; idx < BM * 16; idx += NT) {
        int r = idx >> 4, c4 = (idx & 15) * 4;
        float4 v = *(const float4*)(g + (size_t)r * D_ + c4);
        if (SCALE) { v.x *= 0.125f; v.y *= 0.125f; v.z *= 0.125f; v.w *= 0.125f; }
        uint32_t h0, l0, h1, l1;
        split2pack(v.x, v.y, h0, l0);
        split2pack(v.z, v.w, h1, l1);
        *(uint2*)(smH + r * RB + c4 * 2) = make_uint2(h0, h1);
        *(uint2*)(smL + r * RB + c4 * 2) = make_uint2(l0, l1);
    }
}

// scores for one 16m x 64n chunk (3-split bf16), Q frags in regs
__device__ __forceinline__ void qk_chunk(uint32_t sb, int co, int mi, int l7,
                                         const uint32_t aQH[4][4], const uint32_t aQL[4][4],
                                         float c[8][4]) {
    #pragma unroll
    for (int nf = 0; nf < 8; ++nf)
        #pragma unroll
        for (int i = 0; i < 4; ++i) c[nf][i] = 0.f;

    #pragma unroll
    for (int kc = 0; kc < 4; ++kc) {
        const uint32_t bcol = kc * 32 + (mi & 1) * 16;
        #pragma unroll
        for (int nf2 = 0; nf2 < 4; ++nf2) {
            uint32_t bH[4], bL[4];
            uint32_t brow = (uint32_t)(co + nf2 * 16 + ((mi >> 1) << 3) + l7) * RB;
            ldsm4(bH, sb + OFF_KH + brow + bcol);
            ldsm4(bL, sb + OFF_KL + brow + bcol);
            mma_bf16(c[2 * nf2],     aQH[kc], bH[0], bH[1]);
            mma_bf16(c[2 * nf2 + 1], aQH[kc], bH[2], bH[3]);
            mma_bf16(c[2 * nf2],     aQH[kc], bL[0], bL[1]);
            mma_bf16(c[2 * nf2 + 1], aQH[kc], bL[2], bL[3]);
            mma_bf16(c[2 * nf2],     aQL[kc], bH[0], bH[1]);
            mma_bf16(c[2 * nf2 + 1], aQL[kc], bH[2], bH[3]);
        }
    }
}

__global__ void __launch_bounds__(NT, 2)
sdpa_fused(const float* __restrict__ Q, const float* __restrict__ K,
           const float* __restrict__ V, const int* __restrict__ mask,
           float* __restrict__ out, float* __restrict__ wts)
{
    extern __shared__ char sm[];
    const uint32_t sb = smem_u32(sm);
    const int tid = threadIdx.x, w = tid >> 5, lid = tid & 31;
    const int g = lid >> 2, tl = lid & 3, mi = lid >> 3, l7 = lid & 7;
    const int bh = blockIdx.y, b = bh >> 4, q0 = blockIdx.x * BM;

    const float* Qg = Q + ((size_t)bh * S_ + q0) * D_;
    const float* Kg = K + (size_t)bh * S_ * D_;
    const float* Vg = V + (size_t)bh * S_ * D_;
    const int*   Mg = mask + (size_t)b * S_ * S_;
    float*       Wg = wts + ((size_t)bh * S_ + q0) * S_;
    float*       Og = out + ((size_t)bh * S_ + q0) * D_;

    // Q -> smem (K area), hoist Q fragments to registers
    load_split<true>(Qg, sm + OFF_KH, sm + OFF_KL, tid);
    __syncthreads();

    uint32_t aQH[4][4], aQL[4][4];
    {
        uint32_t arow = (uint32_t)(16 * w + ((mi & 1) << 3) + l7) * RB;
        #pragma unroll
        for (int kc = 0; kc < 4; ++kc) {
            uint32_t acol = kc * 32 + (mi >> 1) * 16;
            ldsm4(aQH[kc], sb + OFF_KH + arow + acol);
            ldsm4(aQL[kc], sb + OFF_KL + arow + acol);
        }
    }

    const int r0 = 16 * w + g;
    const int* m0p = Mg + (size_t)(q0 + r0) * S_;
    const int* m1p = Mg + (size_t)(q0 + r0 + 8) * S_;
    float* w0p = Wg + (size_t)r0 * S_;
    float* w1p = Wg + (size_t)(r0 + 8) * S_;

    float rs0 = 0.f, rs1 = 0.f;
    float o[8][4];
    #pragma unroll
    for (int df = 0; df < 8; ++df)
        #pragma unroll
        for (int i = 0; i < 4; ++i) o[df][i] = 0.f;

    for (int t = 0; t < NTILE; ++t) {
        __syncthreads();
        load_split<false>(Kg + (size_t)t * BN * D_, sm + OFF_KH, sm + OFF_KL, tid);
        load_split<false>(Vg + (size_t)t * BN * D_, sm + OFF_VH, sm + OFF_VL, tid);
        __syncthreads();

        #pragma unroll
        for (int ch2 = 0; ch2 < 2; ++ch2) {
            const int co = 64 * ch2;
            float c[8][4];
            qk_chunk(sb, co, mi, l7, aQH, aQL, c);

            // exp + mask; write raw e to W; accumulate rowsums; c <- e
            const int colb = t * BN + co;
            #pragma unroll
            for (int nf = 0; nf < 8; ++nf) {
                int col = colb + 8 * nf + 2 * tl;
                int2 mA = *(const int2*)(m0p + col);
                int2 mB = *(const int2*)(m1p + col);
                float e0 = mA.x ? __expf(c[nf][0]) : 0.f;
                float e1 = mA.y ? __expf(c[nf][1]) : 0.f;
                float e2 = mB.x ? __expf(c[nf][2]) : 0.f;
                float e3 = mB.y ? __expf(c[nf][3]) : 0.f;
                *(float2*)(w0p + col) = make_float2(e0, e1);
                *(float2*)(w1p + col) = make_float2(e2, e3);
                rs0 += e0 + e1;
                rs1 += e2 + e3;
                c[nf][0] = e0; c[nf][1] = e1; c[nf][2] = e2; c[nf][3] = e3;
            }

            // pack P chunk into PV A-frags
            uint32_t ph[4][4], pl[4][4];
            #pragma unroll
            for (int kc = 0; kc < 4; ++kc) {
                split2pack(c[2*kc][0],   c[2*kc][1],   ph[kc][0], pl[kc][0]);
                split2pack(c[2*kc][2],   c[2*kc][3],   ph[kc][1], pl[kc][1]);
                split2pack(c[2*kc+1][0], c[2*kc+1][1], ph[kc][2], pl[kc][2]);
                split2pack(c[2*kc+1][2], c[2*kc+1][3], ph[kc][3], pl[kc][3]);
            }

            // PV for this 64-key chunk: O += P * V (3-split)
            #pragma unroll
            for (int kc = 0; kc < 4; ++kc) {
                uint32_t vrow = (uint32_t)(co + kc * 16 + ((mi & 1) << 3) + l7) * RB;
                #pragma unroll
                for (int db2 = 0; db2 < 4; ++db2) {
                    uint32_t vh[4], vl[4];
                    uint32_t va = sb + OFF_VH + vrow + db2 * 32 + (mi >> 1) * 16;
                    ldsm4t(vh, va);
                    ldsm4t(vl, va + (OFF_VL - OFF_VH));
                    mma_bf16(o[2 * db2],     ph[kc], vh[0], vh[1]);
                    mma_bf16(o[2 * db2 + 1], ph[kc], vh[2], vh[3]);
                    mma_bf16(o[2 * db2],     ph[kc], vl[0], vl[1]);
                    mma_bf16(o[2 * db2 + 1], ph[kc], vl[2], vl[3]);
                    mma_bf16(o[2 * db2],     pl[kc], vh[0], vh[1]);
                    mma_bf16(o[2 * db2 + 1], pl[kc], vh[2], vh[3]);
                }
            }
        }
    }

    // ---- rowsums -> rinv (smem) ----
    rs0 += __shfl_xor_sync(0xffffffffu, rs0, 1);
    rs0 += __shfl_xor_sync(0xffffffffu, rs0, 2);
    rs1 += __shfl_xor_sync(0xffffffffu, rs1, 1);
    rs1 += __shfl_xor_sync(0xffffffffu, rs1, 2);
    float* rinv = (float*)(sm + OFF_RINV);
    if (tl == 0) {
        rinv[r0]     = rs0;
        rinv[r0 + 8] = rs1;
    }
    __syncthreads();            // also makes all raw-e W stores visible block-wide
    if (tid < 128) rinv[tid] = 1.0f / rinv[tid];
    __syncthreads();

    // ---- O write ----
    const float ri0 = rinv[r0], ri1 = rinv[r0 + 8];
    #pragma unroll
    for (int df = 0; df < 8; ++df) {
        int colc = 8 * df + 2 * tl;
        *(float2*)(Og + (size_t)r0 * D_ + colc) =
            make_float2(o[df][0] * ri0, o[df][1] * ri0);
        *(float2*)(Og + (size_t)(r0 + 8) * D_ + colc) =
            make_float2(o[df][2] * ri1, o[df][3] * ri1);
    }

    // ---- rescale this CTA's W slab in place ----
    for (int idx = tid; idx < BM * (S_ / 4); idx += NT) {
        int r = idx >> 9, c4 = idx & 511;
        float ri = rinv[r];
        float4* p = (float4*)(Wg + (size_t)r * S_) + c4;
        float4 v = *p;
        v.x *= ri; v.y *= ri; v.z *= ri; v.w *= ri;
        *p = v;
    }
}

extern "C" void kernel_launch(void* const* d_in, const int* in_sizes, int n_in,
                              void* d_out, int out_size)
{
    const float* Q    = (const float*)d_in[0];
    const float* K    = (const float*)d_in[1];
    const float* V    = (const float*)d_in[2];
    const int*   mask = (const int*)d_in[3];

    float* out = (float*)d_out;
    float* wts = out + (size_t)B_ * H_ * S_ * D_;

    cudaFuncSetAttribute(sdpa_fused, cudaFuncAttributeMaxDynamicSharedMemorySize, SMEM_SZ);

    dim3 grid(S_ / BM, B_ * H_);
    sdpa_fused<<<grid, NT, SMEM_SZ>>>(Q, K, V, mask, out, wts);
}

// round 8
// speedup vs baseline: 2.5746x; 1.2548x over previous
#include <cuda_runtime.h>
#include <cuda_bf16.h>
#include <cstdint>

// ScaledDotProductAttention B=4,H=16,S=2048,D=64 fp32 + mask [B,1,S,S] int32.
// out [B,H,S,D] then weights [B,H,S,S] concatenated in d_out.
//
// Round 7: fused QK+exp+PV kernel writes raw e to W and rowsums to g_rsum;
// a dedicated full-chip streaming kernel rescales W in place afterwards.
//   k1 (sdpa_fused): QK 3-split bf16 HMMA, exp+mask, raw e -> W, PV 3-split
//       -> O normalized in-kernel; rowsums -> g_rsum.
//   k2 (sdpa_rescale): W[row,:] *= 1/rsum[row], one block per row, float4.

#define B_ 4
#define H_ 16
#define S_ 2048
#define D_ 64

constexpr int BM = 128, BN = 128, NT = 256, NTILE = S_ / BN;
constexpr int RB = 144;                    // bytes per bf16 smem row (72 elems)

constexpr int OFF_KH   = 0;
constexpr int OFF_KL   = OFF_KH + BM * RB;     // 18432
constexpr int OFF_VH   = OFF_KL + BM * RB;     // 36864
constexpr int OFF_VL   = OFF_VH + BM * RB;     // 55296
constexpr int OFF_RINV = OFF_VL + BM * RB;     // 73728
constexpr int SMEM_SZ  = OFF_RINV + 512;       // 74240

__device__ float g_rsum[B_ * H_ * S_];

// ---------- helpers ----------
__device__ __forceinline__ uint32_t smem_u32(const void* p) {
    uint32_t a;
    asm("{ .reg .u64 t; cvta.to.shared.u64 t, %1; cvt.u32.u64 %0, t; }" : "=r"(a) : "l"(p));
    return a;
}
__device__ __forceinline__ void ldsm4(uint32_t* r, uint32_t a) {
    asm volatile("ldmatrix.sync.aligned.m8n8.x4.shared.b16 {%0,%1,%2,%3}, [%4];"
                 : "=r"(r[0]), "=r"(r[1]), "=r"(r[2]), "=r"(r[3]) : "r"(a));
}
__device__ __forceinline__ void ldsm4t(uint32_t* r, uint32_t a) {
    asm volatile("ldmatrix.sync.aligned.m8n8.x4.trans.shared.b16 {%0,%1,%2,%3}, [%4];"
                 : "=r"(r[0]), "=r"(r[1]), "=r"(r[2]), "=r"(r[3]) : "r"(a));
}
__device__ __forceinline__ void mma_bf16(float* c, const uint32_t* a, uint32_t b0, uint32_t b1) {
    asm volatile(
        "mma.sync.aligned.m16n8k16.row.col.f32.bf16.bf16.f32 "
        "{%0,%1,%2,%3}, {%4,%5,%6,%7}, {%8,%9}, {%0,%1,%2,%3};"
        : "+f"(c[0]), "+f"(c[1]), "+f"(c[2]), "+f"(c[3])
        : "r"(a[0]), "r"(a[1]), "r"(a[2]), "r"(a[3]), "r"(b0), "r"(b1));
}
__device__ __forceinline__ void split2pack(float a, float b, uint32_t& hp, uint32_t& lp) {
    __nv_bfloat162 h = __floats2bfloat162_rn(a, b);
    float2 hf = __bfloat1622float2(h);
    __nv_bfloat162 l = __floats2bfloat162_rn(a - hf.x, b - hf.y);
    hp = *(uint32_t*)&h;
    lp = *(uint32_t*)&l;
}
template <bool SCALE>
__device__ __forceinline__ void load_split(const float* __restrict__ g, char* smH, char* smL,
                                           int tid) {
    for (int idx = tid; idx < BM * 16; idx += NT) {
        int r = idx >> 4, c4 = (idx & 15) * 4;
        float4 v = *(const float4*)(g + (size_t)r * D_ + c4);
        if (SCALE) { v.x *= 0.125f; v.y *= 0.125f; v.z *= 0.125f; v.w *= 0.125f; }
        uint32_t h0, l0, h1, l1;
        split2pack(v.x, v.y, h0, l0);
        split2pack(v.z, v.w, h1, l1);
        *(uint2*)(smH + r * RB + c4 * 2) = make_uint2(h0, h1);
        *(uint2*)(smL + r * RB + c4 * 2) = make_uint2(l0, l1);
    }
}

// scores for one 16m x 64n chunk (3-split bf16), Q frags in regs
__device__ __forceinline__ void qk_chunk(uint32_t sb, int co, int mi, int l7,
                                         const uint32_t aQH[4][4], const uint32_t aQL[4][4],
                                         float c[8][4]) {
    #pragma unroll
    for (int nf = 0; nf < 8; ++nf)
        #pragma unroll
        for (int i = 0; i < 4; ++i) c[nf][i] = 0.f;

    #pragma unroll
    for (int kc = 0; kc < 4; ++kc) {
        const uint32_t bcol = kc * 32 + (mi & 1) * 16;
        #pragma unroll
        for (int nf2 = 0; nf2 < 4; ++nf2) {
            uint32_t bH[4], bL[4];
            uint32_t brow = (uint32_t)(co + nf2 * 16 + ((mi >> 1) << 3) + l7) * RB;
            ldsm4(bH, sb + OFF_KH + brow + bcol);
            ldsm4(bL, sb + OFF_KL + brow + bcol);
            mma_bf16(c[2 * nf2],     aQH[kc], bH[0], bH[1]);
            mma_bf16(c[2 * nf2 + 1], aQH[kc], bH[2], bH[3]);
            mma_bf16(c[2 * nf2],     aQH[kc], bL[0], bL[1]);
            mma_bf16(c[2 * nf2 + 1], aQH[kc], bL[2], bL[3]);
            mma_bf16(c[2 * nf2],     aQL[kc], bH[0], bH[1]);
            mma_bf16(c[2 * nf2 + 1], aQL[kc], bH[2], bH[3]);
        }
    }
}

// ---------- k1: fused QK+exp -> raw e in W, PV -> O, rowsums -> g_rsum ----------
__global__ void __launch_bounds__(NT, 2)
sdpa_fused(const float* __restrict__ Q, const float* __restrict__ K,
           const float* __restrict__ V, const int* __restrict__ mask,
           float* __restrict__ out, float* __restrict__ wts)
{
    extern __shared__ char sm[];
    const uint32_t sb = smem_u32(sm);
    const int tid = threadIdx.x, w = tid >> 5, lid = tid & 31;
    const int g = lid >> 2, tl = lid & 3, mi = lid >> 3, l7 = lid & 7;
    const int bh = blockIdx.y, b = bh >> 4, q0 = blockIdx.x * BM;

    const float* Qg = Q + ((size_t)bh * S_ + q0) * D_;
    const float* Kg = K + (size_t)bh * S_ * D_;
    const float* Vg = V + (size_t)bh * S_ * D_;
    const int*   Mg = mask + (size_t)b * S_ * S_;
    float*       Wg = wts + ((size_t)bh * S_ + q0) * S_;
    float*       Og = out + ((size_t)bh * S_ + q0) * D_;

    // Q -> smem (K area), hoist Q fragments to registers
    load_split<true>(Qg, sm + OFF_KH, sm + OFF_KL, tid);
    __syncthreads();

    uint32_t aQH[4][4], aQL[4][4];
    {
        uint32_t arow = (uint32_t)(16 * w + ((mi & 1) << 3) + l7) * RB;
        #pragma unroll
        for (int kc = 0; kc < 4; ++kc) {
            uint32_t acol = kc * 32 + (mi >> 1) * 16;
            ldsm4(aQH[kc], sb + OFF_KH + arow + acol);
            ldsm4(aQL[kc], sb + OFF_KL + arow + acol);
        }
    }

    const int r0 = 16 * w + g;
    const int* m0p = Mg + (size_t)(q0 + r0) * S_;
    const int* m1p = Mg + (size_t)(q0 + r0 + 8) * S_;
    float* w0p = Wg + (size_t)r0 * S_;
    float* w1p = Wg + (size_t)(r0 + 8) * S_;

    float rs0 = 0.f, rs1 = 0.f;
    float o[8][4];
    #pragma unroll
    for (int df = 0; df < 8; ++df)
        #pragma unroll
        for (int i = 0; i < 4; ++i) o[df][i] = 0.f;

    for (int t = 0; t < NTILE; ++t) {
        __syncthreads();
        load_split<false>(Kg + (size_t)t * BN * D_, sm + OFF_KH, sm + OFF_KL, tid);
        load_split<false>(Vg + (size_t)t * BN * D_, sm + OFF_VH, sm + OFF_VL, tid);
        __syncthreads();

        #pragma unroll
        for (int ch2 = 0; ch2 < 2; ++ch2) {
            const int co = 64 * ch2;
            float c[8][4];
            qk_chunk(sb, co, mi, l7, aQH, aQL, c);

            // exp + mask; write raw e to W; accumulate rowsums; c <- e
            const int colb = t * BN + co;
            #pragma unroll
            for (int nf = 0; nf < 8; ++nf) {
                int col = colb + 8 * nf + 2 * tl;
                int2 mA = *(const int2*)(m0p + col);
                int2 mB = *(const int2*)(m1p + col);
                float e0 = mA.x ? __expf(c[nf][0]) : 0.f;
                float e1 = mA.y ? __expf(c[nf][1]) : 0.f;
                float e2 = mB.x ? __expf(c[nf][2]) : 0.f;
                float e3 = mB.y ? __expf(c[nf][3]) : 0.f;
                *(float2*)(w0p + col) = make_float2(e0, e1);
                *(float2*)(w1p + col) = make_float2(e2, e3);
                rs0 += e0 + e1;
                rs1 += e2 + e3;
                c[nf][0] = e0; c[nf][1] = e1; c[nf][2] = e2; c[nf][3] = e3;
            }

            // pack P chunk into PV A-frags
            uint32_t ph[4][4], pl[4][4];
            #pragma unroll
            for (int kc = 0; kc < 4; ++kc) {
                split2pack(c[2*kc][0],   c[2*kc][1],   ph[kc][0], pl[kc][0]);
                split2pack(c[2*kc][2],   c[2*kc][3],   ph[kc][1], pl[kc][1]);
                split2pack(c[2*kc+1][0], c[2*kc+1][1], ph[kc][2], pl[kc][2]);
                split2pack(c[2*kc+1][2], c[2*kc+1][3], ph[kc][3], pl[kc][3]);
            }

            // PV for this 64-key chunk: O += P * V (3-split)
            #pragma unroll
            for (int kc = 0; kc < 4; ++kc) {
                uint32_t vrow = (uint32_t)(co + kc * 16 + ((mi & 1) << 3) + l7) * RB;
                #pragma unroll
                for (int db2 = 0; db2 < 4; ++db2) {
                    uint32_t vh[4], vl[4];
                    uint32_t va = sb + OFF_VH + vrow + db2 * 32 + (mi >> 1) * 16;
                    ldsm4t(vh, va);
                    ldsm4t(vl, va + (OFF_VL - OFF_VH));
                    mma_bf16(o[2 * db2],     ph[kc], vh[0], vh[1]);
                    mma_bf16(o[2 * db2 + 1], ph[kc], vh[2], vh[3]);
                    mma_bf16(o[2 * db2],     ph[kc], vl[0], vl[1]);
                    mma_bf16(o[2 * db2 + 1], ph[kc], vl[2], vl[3]);
                    mma_bf16(o[2 * db2],     pl[kc], vh[0], vh[1]);
                    mma_bf16(o[2 * db2 + 1], pl[kc], vh[2], vh[3]);
                }
            }
        }
    }

    // ---- rowsums: quad-reduce, publish to g_rsum + smem ----
    rs0 += __shfl_xor_sync(0xffffffffu, rs0, 1);
    rs0 += __shfl_xor_sync(0xffffffffu, rs0, 2);
    rs1 += __shfl_xor_sync(0xffffffffu, rs1, 1);
    rs1 += __shfl_xor_sync(0xffffffffu, rs1, 2);
    float* rinv = (float*)(sm + OFF_RINV);
    if (tl == 0) {
        rinv[r0]     = rs0;
        rinv[r0 + 8] = rs1;
        g_rsum[(size_t)bh * S_ + q0 + r0]     = rs0;
        g_rsum[(size_t)bh * S_ + q0 + r0 + 8] = rs1;
    }
    __syncthreads();

    // ---- O write (normalized) ----
    const float ri0 = 1.0f / rinv[r0], ri1 = 1.0f / rinv[r0 + 8];
    #pragma unroll
    for (int df = 0; df < 8; ++df) {
        int colc = 8 * df + 2 * tl;
        *(float2*)(Og + (size_t)r0 * D_ + colc) =
            make_float2(o[df][0] * ri0, o[df][1] * ri0);
        *(float2*)(Og + (size_t)(r0 + 8) * D_ + colc) =
            make_float2(o[df][2] * ri1, o[df][3] * ri1);
    }
}

// ---------- k2: streaming W rescale (one block per row) ----------
__global__ void __launch_bounds__(256, 8)
sdpa_rescale(float* __restrict__ wts)
{
    const int row = blockIdx.x;                 // 0 .. B*H*S-1
    const float ri = 1.0f / g_rsum[row];
    float4* p = (float4*)(wts + (size_t)row * S_);
    const int tid = threadIdx.x;
    #pragma unroll
    for (int i = 0; i < 2; ++i) {
        float4 v = p[tid + 256 * i];
        v.x *= ri; v.y *= ri; v.z *= ri; v.w *= ri;
        p[tid + 256 * i] = v;
    }
}

extern "C" void kernel_launch(void* const* d_in, const int* in_sizes, int n_in,
                              void* d_out, int out_size)
{
    const float* Q    = (const float*)d_in[0];
    const float* K    = (const float*)d_in[1];
    const float* V    = (const float*)d_in[2];
    const int*   mask = (const int*)d_in[3];

    float* out = (float*)d_out;
    float* wts = out + (size_t)B_ * H_ * S_ * D_;

    cudaFuncSetAttribute(sdpa_fused, cudaFuncAttributeMaxDynamicSharedMemorySize, SMEM_SZ);

    dim3 grid(S_ / BM, B_ * H_);
    sdpa_fused<<<grid, NT, SMEM_SZ>>>(Q, K, V, mask, out, wts);
    sdpa_rescale<<<B_ * H_ * S_, 256>>>(wts);
}

// round 9
// speedup vs baseline: 2.6142x; 1.0154x over previous
#include <cuda_runtime.h>
#include <cuda_fp16.h>
#include <cstdint>

// ScaledDotProductAttention B=4,H=16,S=2048,D=64 fp32 + mask [B,1,S,S] int32.
// out [B,H,S,D] then weights [B,H,S,S] concatenated in d_out.
//
// Round 8: fp16 HMMA (was bf16). QK = 3-term fp16 split (err ~2^-22).
// PV = P split hi/lo x V-hi-only (V rounding 2^-12 -> out rel err ~2.4e-4).
// VL buffer gone: -25% LDSM, -17% MMA, smem 74KB -> 55KB.
//   k1 (sdpa_fused): QK+exp+mask -> raw e to W, PV -> normalized O, rowsums.
//   k2 (sdpa_rescale): W[row,:] *= 1/rsum[row] (DRAM-saturated streaming).

#define B_ 4
#define H_ 16
#define S_ 2048
#define D_ 64

constexpr int BM = 128, BN = 128, NT = 256, NTILE = S_ / BN;
constexpr int RB = 144;                    // bytes per fp16 smem row (72 elems)

constexpr int OFF_KH   = 0;
constexpr int OFF_KL   = OFF_KH + BM * RB;     // 18432
constexpr int OFF_VH   = OFF_KL + BM * RB;     // 36864
constexpr int OFF_RINV = OFF_VH + BM * RB;     // 55296
constexpr int SMEM_SZ  = OFF_RINV + 512;       // 55808

__device__ float g_rsum[B_ * H_ * S_];

// ---------- helpers ----------
__device__ __forceinline__ uint32_t smem_u32(const void* p) {
    uint32_t a;
    asm("{ .reg .u64 t; cvta.to.shared.u64 t, %1; cvt.u32.u64 %0, t; }" : "=r"(a) : "l"(p));
    return a;
}
__device__ __forceinline__ void ldsm4(uint32_t* r, uint32_t a) {
    asm volatile("ldmatrix.sync.aligned.m8n8.x4.shared.b16 {%0,%1,%2,%3}, [%4];"
                 : "=r"(r[0]), "=r"(r[1]), "=r"(r[2]), "=r"(r[3]) : "r"(a));
}
__device__ __forceinline__ void ldsm4t(uint32_t* r, uint32_t a) {
    asm volatile("ldmatrix.sync.aligned.m8n8.x4.trans.shared.b16 {%0,%1,%2,%3}, [%4];"
                 : "=r"(r[0]), "=r"(r[1]), "=r"(r[2]), "=r"(r[3]) : "r"(a));
}
__device__ __forceinline__ void mma_f16(float* c, const uint32_t* a, uint32_t b0, uint32_t b1) {
    asm volatile(
        "mma.sync.aligned.m16n8k16.row.col.f32.f16.f16.f32 "
        "{%0,%1,%2,%3}, {%4,%5,%6,%7}, {%8,%9}, {%0,%1,%2,%3};"
        : "+f"(c[0]), "+f"(c[1]), "+f"(c[2]), "+f"(c[3])
        : "r"(a[0]), "r"(a[1]), "r"(a[2]), "r"(a[3]), "r"(b0), "r"(b1));
}
__device__ __forceinline__ uint32_t pack_h2(float a, float b) {
    __half2 h = __floats2half2_rn(a, b);
    return *(uint32_t*)&h;
}
__device__ __forceinline__ void split2pack(float a, float b, uint32_t& hp, uint32_t& lp) {
    __half2 h = __floats2half2_rn(a, b);
    float2 hf = __half22float2(h);
    __half2 l = __floats2half2_rn(a - hf.x, b - hf.y);
    hp = *(uint32_t*)&h;
    lp = *(uint32_t*)&l;
}
// f32 [128][64] -> fp16 hi + lo smem (for Q and K)
template <bool SCALE>
__device__ __forceinline__ void load_split(const float* __restrict__ g, char* smH, char* smL,
                                           int tid) {
    for (int idx = tid; idx < BM * 16; idx += NT) {
        int r = idx >> 4, c4 = (idx & 15) * 4;
        float4 v = *(const float4*)(g + (size_t)r * D_ + c4);
        if (SCALE) { v.x *= 0.125f; v.y *= 0.125f; v.z *= 0.125f; v.w *= 0.125f; }
        uint32_t h0, l0, h1, l1;
        split2pack(v.x, v.y, h0, l0);
        split2pack(v.z, v.w, h1, l1);
        *(uint2*)(smH + r * RB + c4 * 2) = make_uint2(h0, h1);
        *(uint2*)(smL + r * RB + c4 * 2) = make_uint2(l0, l1);
    }
}
// f32 [128][64] -> fp16 hi-only smem (for V)
__device__ __forceinline__ void load_hi(const float* __restrict__ g, char* smH, int tid) {
    for (int idx = tid; idx < BM * 16; idx += NT) {
        int r = idx >> 4, c4 = (idx & 15) * 4;
        float4 v = *(const float4*)(g + (size_t)r * D_ + c4);
        *(uint2*)(smH + r * RB + c4 * 2) =
            make_uint2(pack_h2(v.x, v.y), pack_h2(v.z, v.w));
    }
}

// scores for one 16m x 64n chunk (3-term fp16 split), Q frags in regs
__device__ __forceinline__ void qk_chunk(uint32_t sb, int co, int mi, int l7,
                                         const uint32_t aQH[4][4], const uint32_t aQL[4][4],
                                         float c[8][4]) {
    #pragma unroll
    for (int nf = 0; nf < 8; ++nf)
        #pragma unroll
        for (int i = 0; i < 4; ++i) c[nf][i] = 0.f;

    #pragma unroll
    for (int kc = 0; kc < 4; ++kc) {
        const uint32_t bcol = kc * 32 + (mi & 1) * 16;
        #pragma unroll
        for (int nf2 = 0; nf2 < 4; ++nf2) {
            uint32_t bH[4], bL[4];
            uint32_t brow = (uint32_t)(co + nf2 * 16 + ((mi >> 1) << 3) + l7) * RB;
            ldsm4(bH, sb + OFF_KH + brow + bcol);
            ldsm4(bL, sb + OFF_KL + brow + bcol);
            mma_f16(c[2 * nf2],     aQH[kc], bH[0], bH[1]);
            mma_f16(c[2 * nf2 + 1], aQH[kc], bH[2], bH[3]);
            mma_f16(c[2 * nf2],     aQH[kc], bL[0], bL[1]);
            mma_f16(c[2 * nf2 + 1], aQH[kc], bL[2], bL[3]);
            mma_f16(c[2 * nf2],     aQL[kc], bH[0], bH[1]);
            mma_f16(c[2 * nf2 + 1], aQL[kc], bH[2], bH[3]);
        }
    }
}

// ---------- k1: fused QK+exp -> raw e in W, PV -> O, rowsums -> g_rsum ----------
__global__ void __launch_bounds__(NT, 2)
sdpa_fused(const float* __restrict__ Q, const float* __restrict__ K,
           const float* __restrict__ V, const int* __restrict__ mask,
           float* __restrict__ out, float* __restrict__ wts)
{
    extern __shared__ char sm[];
    const uint32_t sb = smem_u32(sm);
    const int tid = threadIdx.x, w = tid >> 5, lid = tid & 31;
    const int g = lid >> 2, tl = lid & 3, mi = lid >> 3, l7 = lid & 7;
    const int bh = blockIdx.y, b = bh >> 4, q0 = blockIdx.x * BM;

    const float* Qg = Q + ((size_t)bh * S_ + q0) * D_;
    const float* Kg = K + (size_t)bh * S_ * D_;
    const float* Vg = V + (size_t)bh * S_ * D_;
    const int*   Mg = mask + (size_t)b * S_ * S_;
    float*       Wg = wts + ((size_t)bh * S_ + q0) * S_;
    float*       Og = out + ((size_t)bh * S_ + q0) * D_;

    // Q -> smem (K area), hoist Q fragments to registers
    load_split<true>(Qg, sm + OFF_KH, sm + OFF_KL, tid);
    __syncthreads();

    uint32_t aQH[4][4], aQL[4][4];
    {
        uint32_t arow = (uint32_t)(16 * w + ((mi & 1) << 3) + l7) * RB;
        #pragma unroll
        for (int kc = 0; kc < 4; ++kc) {
            uint32_t acol = kc * 32 + (mi >> 1) * 16;
            ldsm4(aQH[kc], sb + OFF_KH + arow + acol);
            ldsm4(aQL[kc], sb + OFF_KL + arow + acol);
        }
    }

    const int r0 = 16 * w + g;
    const int* m0p = Mg + (size_t)(q0 + r0) * S_;
    const int* m1p = Mg + (size_t)(q0 + r0 + 8) * S_;
    float* w0p = Wg + (size_t)r0 * S_;
    float* w1p = Wg + (size_t)(r0 + 8) * S_;

    float rs0 = 0.f, rs1 = 0.f;
    float o[8][4];
    #pragma unroll
    for (int df = 0; df < 8; ++df)
        #pragma unroll
        for (int i = 0; i < 4; ++i) o[df][i] = 0.f;

    for (int t = 0; t < NTILE; ++t) {
        __syncthreads();
        load_split<false>(Kg + (size_t)t * BN * D_, sm + OFF_KH, sm + OFF_KL, tid);
        load_hi(Vg + (size_t)t * BN * D_, sm + OFF_VH, tid);
        __syncthreads();

        #pragma unroll
        for (int ch2 = 0; ch2 < 2; ++ch2) {
            const int co = 64 * ch2;
            float c[8][4];
            qk_chunk(sb, co, mi, l7, aQH, aQL, c);

            // exp + mask; write raw e to W; accumulate rowsums; c <- e
            const int colb = t * BN + co;
            #pragma unroll
            for (int nf = 0; nf < 8; ++nf) {
                int col = colb + 8 * nf + 2 * tl;
                int2 mA = *(const int2*)(m0p + col);
                int2 mB = *(const int2*)(m1p + col);
                float e0 = mA.x ? __expf(c[nf][0]) : 0.f;
                float e1 = mA.y ? __expf(c[nf][1]) : 0.f;
                float e2 = mB.x ? __expf(c[nf][2]) : 0.f;
                float e3 = mB.y ? __expf(c[nf][3]) : 0.f;
                *(float2*)(w0p + col) = make_float2(e0, e1);
                *(float2*)(w1p + col) = make_float2(e2, e3);
                rs0 += e0 + e1;
                rs1 += e2 + e3;
                c[nf][0] = e0; c[nf][1] = e1; c[nf][2] = e2; c[nf][3] = e3;
            }

            // pack P chunk into PV A-frags (fp16 hi/lo)
            uint32_t ph[4][4], pl[4][4];
            #pragma unroll
            for (int kc = 0; kc < 4; ++kc) {
                split2pack(c[2*kc][0],   c[2*kc][1],   ph[kc][0], pl[kc][0]);
                split2pack(c[2*kc][2],   c[2*kc][3],   ph[kc][1], pl[kc][1]);
                split2pack(c[2*kc+1][0], c[2*kc+1][1], ph[kc][2], pl[kc][2]);
                split2pack(c[2*kc+1][2], c[2*kc+1][3], ph[kc][3], pl[kc][3]);
            }

            // PV for this 64-key chunk: O += (Ph + Pl) * Vh
            #pragma unroll
            for (int kc = 0; kc < 4; ++kc) {
                uint32_t vrow = (uint32_t)(co + kc * 16 + ((mi & 1) << 3) + l7) * RB;
                #pragma unroll
                for (int db2 = 0; db2 < 4; ++db2) {
                    uint32_t vh[4];
                    ldsm4t(vh, sb + OFF_VH + vrow + db2 * 32 + (mi >> 1) * 16);
                    mma_f16(o[2 * db2],     ph[kc], vh[0], vh[1]);
                    mma_f16(o[2 * db2 + 1], ph[kc], vh[2], vh[3]);
                    mma_f16(o[2 * db2],     pl[kc], vh[0], vh[1]);
                    mma_f16(o[2 * db2 + 1], pl[kc], vh[2], vh[3]);
                }
            }
        }
    }

    // ---- rowsums: quad-reduce, publish to g_rsum + smem ----
    rs0 += __shfl_xor_sync(0xffffffffu, rs0, 1);
    rs0 += __shfl_xor_sync(0xffffffffu, rs0, 2);
    rs1 += __shfl_xor_sync(0xffffffffu, rs1, 1);
    rs1 += __shfl_xor_sync(0xffffffffu, rs1, 2);
    float* rinv = (float*)(sm + OFF_RINV);
    if (tl == 0) {
        rinv[r0]     = rs0;
        rinv[r0 + 8] = rs1;
        g_rsum[(size_t)bh * S_ + q0 + r0]     = rs0;
        g_rsum[(size_t)bh * S_ + q0 + r0 + 8] = rs1;
    }
    __syncthreads();

    // ---- O write (normalized) ----
    const float ri0 = 1.0f / rinv[r0], ri1 = 1.0f / rinv[r0 + 8];
    #pragma unroll
    for (int df = 0; df < 8; ++df) {
        int colc = 8 * df + 2 * tl;
        *(float2*)(Og + (size_t)r0 * D_ + colc) =
            make_float2(o[df][0] * ri0, o[df][1] * ri0);
        *(float2*)(Og + (size_t)(r0 + 8) * D_ + colc) =
            make_float2(o[df][2] * ri1, o[df][3] * ri1);
    }
}

// ---------- k2: streaming W rescale (one block per row) ----------
__global__ void __launch_bounds__(256, 8)
sdpa_rescale(float* __restrict__ wts)
{
    const int row = blockIdx.x;                 // 0 .. B*H*S-1
    const float ri = 1.0f / g_rsum[row];
    float4* p = (float4*)(wts + (size_t)row * S_);
    const int tid = threadIdx.x;
    #pragma unroll
    for (int i = 0; i < 2; ++i) {
        float4 v = p[tid + 256 * i];
        v.x *= ri; v.y *= ri; v.z *= ri; v.w *= ri;
        p[tid + 256 * i] = v;
    }
}

extern "C" void kernel_launch(void* const* d_in, const int* in_sizes, int n_in,
                              void* d_out, int out_size)
{
    const float* Q    = (const float*)d_in[0];
    const float* K    = (const float*)d_in[1];
    const float* V    = (const float*)d_in[2];
    const int*   mask = (const int*)d_in[3];

    float* out = (float*)d_out;
    float* wts = out + (size_t)B_ * H_ * S_ * D_;

    cudaFuncSetAttribute(sdpa_fused, cudaFuncAttributeMaxDynamicSharedMemorySize, SMEM_SZ);

    dim3 grid(S_ / BM, B_ * H_);
    sdpa_fused<<<grid, NT, SMEM_SZ>>>(Q, K, V, mask, out, wts);
    sdpa_rescale<<<B_ * H_ * S_, 256>>>(wts);
}

// round 10
// speedup vs baseline: 2.9159x; 1.1154x over previous
#include <cuda_runtime.h>
#include <cuda_fp16.h>
#include <cstdint>

// ScaledDotProductAttention B=4,H=16,S=2048,D=64 fp32 + mask [B,1,S,S] int32.
// out [B,H,S,D] then weights [B,H,S,S] concatenated in d_out.
//
// Round 9: fp16 HMMA, hi-only K/V/P (Q kept split).
//   QK = (Qh+Ql)·Kh   (K rounding err ~2.4e-4 on scores)
//   PV = Ph·Vh        (P,V rounding err ~2.4e-4 each on out)
// Mask int2 loads hoisted ahead of each chunk's QK MMAs (latency hidden).
//   k1 (sdpa_fused): QK+exp+mask -> raw e to W, PV -> normalized O, rowsums.
//   k2 (sdpa_rescale): W[row,:] *= 1/rsum[row] (DRAM-saturated streaming).

#define B_ 4
#define H_ 16
#define S_ 2048
#define D_ 64

constexpr int BM = 128, BN = 128, NT = 256, NTILE = S_ / BN;
constexpr int RB = 144;                    // bytes per fp16 smem row (72 elems)

constexpr int OFF_QL   = 0;                    // Q-lo (only used in prologue area reuse)
constexpr int OFF_KH   = 0;                    // K-hi (reuses Q-hi area after prologue)
constexpr int OFF_QH   = 0;
constexpr int OFF_QL2  = BM * RB;              // 18432 (Q-lo during prologue = V area)
constexpr int OFF_VH   = BM * RB;              // 18432
constexpr int OFF_RINV = 2 * BM * RB;          // 36864
constexpr int SMEM_SZ  = OFF_RINV + 512;       // 37376

__device__ float g_rsum[B_ * H_ * S_];

// ---------- helpers ----------
__device__ __forceinline__ uint32_t smem_u32(const void* p) {
    uint32_t a;
    asm("{ .reg .u64 t; cvta.to.shared.u64 t, %1; cvt.u32.u64 %0, t; }" : "=r"(a) : "l"(p));
    return a;
}
__device__ __forceinline__ void ldsm4(uint32_t* r, uint32_t a) {
    asm volatile("ldmatrix.sync.aligned.m8n8.x4.shared.b16 {%0,%1,%2,%3}, [%4];"
                 : "=r"(r[0]), "=r"(r[1]), "=r"(r[2]), "=r"(r[3]) : "r"(a));
}
__device__ __forceinline__ void ldsm4t(uint32_t* r, uint32_t a) {
    asm volatile("ldmatrix.sync.aligned.m8n8.x4.trans.shared.b16 {%0,%1,%2,%3}, [%4];"
                 : "=r"(r[0]), "=r"(r[1]), "=r"(r[2]), "=r"(r[3]) : "r"(a));
}
__device__ __forceinline__ void mma_f16(float* c, const uint32_t* a, uint32_t b0, uint32_t b1) {
    asm volatile(
        "mma.sync.aligned.m16n8k16.row.col.f32.f16.f16.f32 "
        "{%0,%1,%2,%3}, {%4,%5,%6,%7}, {%8,%9}, {%0,%1,%2,%3};"
        : "+f"(c[0]), "+f"(c[1]), "+f"(c[2]), "+f"(c[3])
        : "r"(a[0]), "r"(a[1]), "r"(a[2]), "r"(a[3]), "r"(b0), "r"(b1));
}
__device__ __forceinline__ uint32_t pack_h2(float a, float b) {
    __half2 h = __floats2half2_rn(a, b);
    return *(uint32_t*)&h;
}
__device__ __forceinline__ void split2pack(float a, float b, uint32_t& hp, uint32_t& lp) {
    __half2 h = __floats2half2_rn(a, b);
    float2 hf = __half22float2(h);
    __half2 l = __floats2half2_rn(a - hf.x, b - hf.y);
    hp = *(uint32_t*)&h;
    lp = *(uint32_t*)&l;
}
// f32 [128][64] -> fp16 hi + lo smem (Q prologue only)
__device__ __forceinline__ void load_split_q(const float* __restrict__ g, char* smH, char* smL,
                                             int tid) {
    for (int idx = tid; idx < BM * 16; idx += NT) {
        int r = idx >> 4, c4 = (idx & 15) * 4;
        float4 v = *(const float4*)(g + (size_t)r * D_ + c4);
        v.x *= 0.125f; v.y *= 0.125f; v.z *= 0.125f; v.w *= 0.125f;
        uint32_t h0, l0, h1, l1;
        split2pack(v.x, v.y, h0, l0);
        split2pack(v.z, v.w, h1, l1);
        *(uint2*)(smH + r * RB + c4 * 2) = make_uint2(h0, h1);
        *(uint2*)(smL + r * RB + c4 * 2) = make_uint2(l0, l1);
    }
}
// f32 [128][64] -> fp16 hi-only smem (K and V tiles)
__device__ __forceinline__ void load_hi(const float* __restrict__ g, char* smH, int tid) {
    for (int idx = tid; idx < BM * 16; idx += NT) {
        int r = idx >> 4, c4 = (idx & 15) * 4;
        float4 v = *(const float4*)(g + (size_t)r * D_ + c4);
        *(uint2*)(smH + r * RB + c4 * 2) =
            make_uint2(pack_h2(v.x, v.y), pack_h2(v.z, v.w));
    }
}

// ---------- k1: fused QK+exp -> raw e in W, PV -> O, rowsums -> g_rsum ----------
__global__ void __launch_bounds__(NT, 2)
sdpa_fused(const float* __restrict__ Q, const float* __restrict__ K,
           const float* __restrict__ V, const int* __restrict__ mask,
           float* __restrict__ out, float* __restrict__ wts)
{
    extern __shared__ char sm[];
    const uint32_t sb = smem_u32(sm);
    const int tid = threadIdx.x, w = tid >> 5, lid = tid & 31;
    const int g = lid >> 2, tl = lid & 3, mi = lid >> 3, l7 = lid & 7;
    const int bh = blockIdx.y, b = bh >> 4, q0 = blockIdx.x * BM;

    const float* Qg = Q + ((size_t)bh * S_ + q0) * D_;
    const float* Kg = K + (size_t)bh * S_ * D_;
    const float* Vg = V + (size_t)bh * S_ * D_;
    const int*   Mg = mask + (size_t)b * S_ * S_;
    float*       Wg = wts + ((size_t)bh * S_ + q0) * S_;
    float*       Og = out + ((size_t)bh * S_ + q0) * D_;

    // prologue: Q split -> smem (KH and VH areas), hoist Q frags to regs
    load_split_q(Qg, sm + OFF_QH, sm + OFF_QL2, tid);
    __syncthreads();

    uint32_t aQH[4][4], aQL[4][4];
    {
        uint32_t arow = (uint32_t)(16 * w + ((mi & 1) << 3) + l7) * RB;
        #pragma unroll
        for (int kc = 0; kc < 4; ++kc) {
            uint32_t acol = kc * 32 + (mi >> 1) * 16;
            ldsm4(aQH[kc], sb + OFF_QH  + arow + acol);
            ldsm4(aQL[kc], sb + OFF_QL2 + arow + acol);
        }
    }

    const int r0 = 16 * w + g;
    const int* m0p = Mg + (size_t)(q0 + r0) * S_;
    const int* m1p = Mg + (size_t)(q0 + r0 + 8) * S_;
    float* w0p = Wg + (size_t)r0 * S_;
    float* w1p = Wg + (size_t)(r0 + 8) * S_;

    float rs0 = 0.f, rs1 = 0.f;
    float o[8][4];
    #pragma unroll
    for (int df = 0; df < 8; ++df)
        #pragma unroll
        for (int i = 0; i < 4; ++i) o[df][i] = 0.f;

    for (int t = 0; t < NTILE; ++t) {
        __syncthreads();
        load_hi(Kg + (size_t)t * BN * D_, sm + OFF_KH, tid);
        load_hi(Vg + (size_t)t * BN * D_, sm + OFF_VH, tid);
        __syncthreads();

        #pragma unroll
        for (int ch2 = 0; ch2 < 2; ++ch2) {
            const int co = 64 * ch2;
            const int colb = t * BN + co;

            // hoist mask loads: in flight during QK MMAs
            int2 mA[8], mB[8];
            #pragma unroll
            for (int nf = 0; nf < 8; ++nf) {
                int col = colb + 8 * nf + 2 * tl;
                mA[nf] = *(const int2*)(m0p + col);
                mB[nf] = *(const int2*)(m1p + col);
            }

            // QK scores: (Qh + Ql) * Kh
            float c[8][4];
            #pragma unroll
            for (int nf = 0; nf < 8; ++nf)
                #pragma unroll
                for (int i = 0; i < 4; ++i) c[nf][i] = 0.f;
            #pragma unroll
            for (int kc = 0; kc < 4; ++kc) {
                const uint32_t bcol = kc * 32 + (mi & 1) * 16;
                #pragma unroll
                for (int nf2 = 0; nf2 < 4; ++nf2) {
                    uint32_t bH[4];
                    uint32_t brow = (uint32_t)(co + nf2 * 16 + ((mi >> 1) << 3) + l7) * RB;
                    ldsm4(bH, sb + OFF_KH + brow + bcol);
                    mma_f16(c[2 * nf2],     aQH[kc], bH[0], bH[1]);
                    mma_f16(c[2 * nf2 + 1], aQH[kc], bH[2], bH[3]);
                    mma_f16(c[2 * nf2],     aQL[kc], bH[0], bH[1]);
                    mma_f16(c[2 * nf2 + 1], aQL[kc], bH[2], bH[3]);
                }
            }

            // exp + mask; write raw e to W; rowsums; pack P-hi frags
            uint32_t ph[4][4];
            #pragma unroll
            for (int nf = 0; nf < 8; ++nf) {
                int col = colb + 8 * nf + 2 * tl;
                float e0 = mA[nf].x ? __expf(c[nf][0]) : 0.f;
                float e1 = mA[nf].y ? __expf(c[nf][1]) : 0.f;
                float e2 = mB[nf].x ? __expf(c[nf][2]) : 0.f;
                float e3 = mB[nf].y ? __expf(c[nf][3]) : 0.f;
                *(float2*)(w0p + col) = make_float2(e0, e1);
                *(float2*)(w1p + col) = make_float2(e2, e3);
                rs0 += e0 + e1;
                rs1 += e2 + e3;
                ph[nf >> 1][((nf & 1) << 1) | 0] = pack_h2(e0, e1);
                ph[nf >> 1][((nf & 1) << 1) | 1] = pack_h2(e2, e3);
            }

            // PV: O += Ph * Vh
            #pragma unroll
            for (int kc = 0; kc < 4; ++kc) {
                uint32_t vrow = (uint32_t)(co + kc * 16 + ((mi & 1) << 3) + l7) * RB;
                #pragma unroll
                for (int db2 = 0; db2 < 4; ++db2) {
                    uint32_t vh[4];
                    ldsm4t(vh, sb + OFF_VH + vrow + db2 * 32 + (mi >> 1) * 16);
                    mma_f16(o[2 * db2],     ph[kc], vh[0], vh[1]);
                    mma_f16(o[2 * db2 + 1], ph[kc], vh[2], vh[3]);
                }
            }
        }
    }

    // ---- rowsums: quad-reduce, publish to g_rsum + smem ----
    rs0 += __shfl_xor_sync(0xffffffffu, rs0, 1);
    rs0 += __shfl_xor_sync(0xffffffffu, rs0, 2);
    rs1 += __shfl_xor_sync(0xffffffffu, rs1, 1);
    rs1 += __shfl_xor_sync(0xffffffffu, rs1, 2);
    float* rinv = (float*)(sm + OFF_RINV);
    if (tl == 0) {
        rinv[r0]     = rs0;
        rinv[r0 + 8] = rs1;
        g_rsum[(size_t)bh * S_ + q0 + r0]     = rs0;
        g_rsum[(size_t)bh * S_ + q0 + r0 + 8] = rs1;
    }
    __syncthreads();

    // ---- O write (normalized) ----
    const float ri0 = 1.0f / rinv[r0], ri1 = 1.0f / rinv[r0 + 8];
    #pragma unroll
    for (int df = 0; df < 8; ++df) {
        int colc = 8 * df + 2 * tl;
        *(float2*)(Og + (size_t)r0 * D_ + colc) =
            make_float2(o[df][0] * ri0, o[df][1] * ri0);
        *(float2*)(Og + (size_t)(r0 + 8) * D_ + colc) =
            make_float2(o[df][2] * ri1, o[df][3] * ri1);
    }
}

// ---------- k2: streaming W rescale (one block per row) ----------
__global__ void __launch_bounds__(256, 8)
sdpa_rescale(float* __restrict__ wts)
{
    const int row = blockIdx.x;                 // 0 .. B*H*S-1
    const float ri = 1.0f / g_rsum[row];
    float4* p = (float4*)(wts + (size_t)row * S_);
    const int tid = threadIdx.x;
    #pragma unroll
    for (int i = 0; i < 2; ++i) {
        float4 v = p[tid + 256 * i];
        v.x *= ri; v.y *= ri; v.z *= ri; v.w *= ri;
        p[tid + 256 * i] = v;
    }
}

extern "C" void kernel_launch(void* const* d_in, const int* in_sizes, int n_in,
                              void* d_out, int out_size)
{
    const float* Q    = (const float*)d_in[0];
    const float* K    = (const float*)d_in[1];
    const float* V    = (const float*)d_in[2];
    const int*   mask = (const int*)d_in[3];

    float* out = (float*)d_out;
    float* wts = out + (size_t)B_ * H_ * S_ * D_;

    cudaFuncSetAttribute(sdpa_fused, cudaFuncAttributeMaxDynamicSharedMemorySize, SMEM_SZ);

    dim3 grid(S_ / BM, B_ * H_);
    sdpa_fused<<<grid, NT, SMEM_SZ>>>(Q, K, V, mask, out, wts);
    sdpa_rescale<<<B_ * H_ * S_, 256>>>(wts);
}

// round 11
// speedup vs baseline: 3.0881x; 1.0591x over previous
#include <cuda_runtime.h>
#include <cuda_fp16.h>
#include <cstdint>

// ScaledDotProductAttention B=4,H=16,S=2048,D=64 fp32 + mask [B,1,S,S] int32.
// out [B,H,S,D] then weights [B,H,S,S] concatenated in d_out.
//
// Round 10: fp16 HMMA, hi-only everywhere (Q, K, V, P all single-term).
//   QK = Qh·Kh, PV = Ph·Vh. Per-term rounding ~2.4e-4, RSS ~4.4e-4 (<1e-3).
// Per warp per tile: 128 MMA, 64 LDSM, 64 exp. Mask loads hoisted.
//   k1 (sdpa_fused): QK+exp+mask -> raw e to W, PV -> normalized O, rowsums.
//   k2 (sdpa_rescale): W[row,:] *= 1/rsum[row] (DRAM-saturated streaming).

#define B_ 4
#define H_ 16
#define S_ 2048
#define D_ 64

constexpr int BM = 128, BN = 128, NT = 256, NTILE = S_ / BN;
constexpr int RB = 144;                    // bytes per fp16 smem row (72 elems)

constexpr int OFF_KH   = 0;                    // K-hi (Q-hi lives here in prologue)
constexpr int OFF_VH   = BM * RB;              // 18432
constexpr int OFF_RINV = 2 * BM * RB;          // 36864
constexpr int SMEM_SZ  = OFF_RINV + 512;       // 37376

__device__ float g_rsum[B_ * H_ * S_];

// ---------- helpers ----------
__device__ __forceinline__ uint32_t smem_u32(const void* p) {
    uint32_t a;
    asm("{ .reg .u64 t; cvta.to.shared.u64 t, %1; cvt.u32.u64 %0, t; }" : "=r"(a) : "l"(p));
    return a;
}
__device__ __forceinline__ void ldsm4(uint32_t* r, uint32_t a) {
    asm volatile("ldmatrix.sync.aligned.m8n8.x4.shared.b16 {%0,%1,%2,%3}, [%4];"
                 : "=r"(r[0]), "=r"(r[1]), "=r"(r[2]), "=r"(r[3]) : "r"(a));
}
__device__ __forceinline__ void ldsm4t(uint32_t* r, uint32_t a) {
    asm volatile("ldmatrix.sync.aligned.m8n8.x4.trans.shared.b16 {%0,%1,%2,%3}, [%4];"
                 : "=r"(r[0]), "=r"(r[1]), "=r"(r[2]), "=r"(r[3]) : "r"(a));
}
__device__ __forceinline__ void mma_f16(float* c, const uint32_t* a, uint32_t b0, uint32_t b1) {
    asm volatile(
        "mma.sync.aligned.m16n8k16.row.col.f32.f16.f16.f32 "
        "{%0,%1,%2,%3}, {%4,%5,%6,%7}, {%8,%9}, {%0,%1,%2,%3};"
        : "+f"(c[0]), "+f"(c[1]), "+f"(c[2]), "+f"(c[3])
        : "r"(a[0]), "r"(a[1]), "r"(a[2]), "r"(a[3]), "r"(b0), "r"(b1));
}
__device__ __forceinline__ uint32_t pack_h2(float a, float b) {
    __half2 h = __floats2half2_rn(a, b);
    return *(uint32_t*)&h;
}
// f32 [128][64] -> fp16 hi-only smem; optional 1/8 pre-scale (Q)
template <bool SCALE>
__device__ __forceinline__ void load_hi(const float* __restrict__ g, char* smH, int tid) {
    for (int idx = tid; idx < BM * 16; idx += NT) {
        int r = idx >> 4, c4 = (idx & 15) * 4;
        float4 v = *(const float4*)(g + (size_t)r * D_ + c4);
        if (SCALE) { v.x *= 0.125f; v.y *= 0.125f; v.z *= 0.125f; v.w *= 0.125f; }
        *(uint2*)(smH + r * RB + c4 * 2) =
            make_uint2(pack_h2(v.x, v.y), pack_h2(v.z, v.w));
    }
}

// ---------- k1: fused QK+exp -> raw e in W, PV -> O, rowsums -> g_rsum ----------
__global__ void __launch_bounds__(NT, 2)
sdpa_fused(const float* __restrict__ Q, const float* __restrict__ K,
           const float* __restrict__ V, const int* __restrict__ mask,
           float* __restrict__ out, float* __restrict__ wts)
{
    extern __shared__ char sm[];
    const uint32_t sb = smem_u32(sm);
    const int tid = threadIdx.x, w = tid >> 5, lid = tid & 31;
    const int g = lid >> 2, tl = lid & 3, mi = lid >> 3, l7 = lid & 7;
    const int bh = blockIdx.y, b = bh >> 4, q0 = blockIdx.x * BM;

    const float* Qg = Q + ((size_t)bh * S_ + q0) * D_;
    const float* Kg = K + (size_t)bh * S_ * D_;
    const float* Vg = V + (size_t)bh * S_ * D_;
    const int*   Mg = mask + (size_t)b * S_ * S_;
    float*       Wg = wts + ((size_t)bh * S_ + q0) * S_;
    float*       Og = out + ((size_t)bh * S_ + q0) * D_;

    // prologue: Q (scaled, hi-only) -> smem, hoist Q frags to regs
    load_hi<true>(Qg, sm + OFF_KH, tid);
    __syncthreads();

    uint32_t aQH[4][4];
    {
        uint32_t arow = (uint32_t)(16 * w + ((mi & 1) << 3) + l7) * RB;
        #pragma unroll
        for (int kc = 0; kc < 4; ++kc) {
            uint32_t acol = kc * 32 + (mi >> 1) * 16;
            ldsm4(aQH[kc], sb + OFF_KH + arow + acol);
        }
    }

    const int r0 = 16 * w + g;
    const int* m0p = Mg + (size_t)(q0 + r0) * S_;
    const int* m1p = Mg + (size_t)(q0 + r0 + 8) * S_;
    float* w0p = Wg + (size_t)r0 * S_;
    float* w1p = Wg + (size_t)(r0 + 8) * S_;

    float rs0 = 0.f, rs1 = 0.f;
    float o[8][4];
    #pragma unroll
    for (int df = 0; df < 8; ++df)
        #pragma unroll
        for (int i = 0; i < 4; ++i) o[df][i] = 0.f;

    for (int t = 0; t < NTILE; ++t) {
        __syncthreads();
        load_hi<false>(Kg + (size_t)t * BN * D_, sm + OFF_KH, tid);
        load_hi<false>(Vg + (size_t)t * BN * D_, sm + OFF_VH, tid);
        __syncthreads();

        #pragma unroll
        for (int ch2 = 0; ch2 < 2; ++ch2) {
            const int co = 64 * ch2;
            const int colb = t * BN + co;

            // hoist mask loads: in flight during QK MMAs
            int2 mA[8], mB[8];
            #pragma unroll
            for (int nf = 0; nf < 8; ++nf) {
                int col = colb + 8 * nf + 2 * tl;
                mA[nf] = *(const int2*)(m0p + col);
                mB[nf] = *(const int2*)(m1p + col);
            }

            // QK scores: Qh * Kh (single term)
            float c[8][4];
            #pragma unroll
            for (int nf = 0; nf < 8; ++nf)
                #pragma unroll
                for (int i = 0; i < 4; ++i) c[nf][i] = 0.f;
            #pragma unroll
            for (int kc = 0; kc < 4; ++kc) {
                const uint32_t bcol = kc * 32 + (mi & 1) * 16;
                #pragma unroll
                for (int nf2 = 0; nf2 < 4; ++nf2) {
                    uint32_t bH[4];
                    uint32_t brow = (uint32_t)(co + nf2 * 16 + ((mi >> 1) << 3) + l7) * RB;
                    ldsm4(bH, sb + OFF_KH + brow + bcol);
                    mma_f16(c[2 * nf2],     aQH[kc], bH[0], bH[1]);
                    mma_f16(c[2 * nf2 + 1], aQH[kc], bH[2], bH[3]);
                }
            }

            // exp + mask; write raw e to W; rowsums; pack P-hi frags
            uint32_t ph[4][4];
            #pragma unroll
            for (int nf = 0; nf < 8; ++nf) {
                int col = colb + 8 * nf + 2 * tl;
                float e0 = mA[nf].x ? __expf(c[nf][0]) : 0.f;
                float e1 = mA[nf].y ? __expf(c[nf][1]) : 0.f;
                float e2 = mB[nf].x ? __expf(c[nf][2]) : 0.f;
                float e3 = mB[nf].y ? __expf(c[nf][3]) : 0.f;
                *(float2*)(w0p + col) = make_float2(e0, e1);
                *(float2*)(w1p + col) = make_float2(e2, e3);
                rs0 += e0 + e1;
                rs1 += e2 + e3;
                ph[nf >> 1][((nf & 1) << 1) | 0] = pack_h2(e0, e1);
                ph[nf >> 1][((nf & 1) << 1) | 1] = pack_h2(e2, e3);
            }

            // PV: O += Ph * Vh
            #pragma unroll
            for (int kc = 0; kc < 4; ++kc) {
                uint32_t vrow = (uint32_t)(co + kc * 16 + ((mi & 1) << 3) + l7) * RB;
                #pragma unroll
                for (int db2 = 0; db2 < 4; ++db2) {
                    uint32_t vh[4];
                    ldsm4t(vh, sb + OFF_VH + vrow + db2 * 32 + (mi >> 1) * 16);
                    mma_f16(o[2 * db2],     ph[kc], vh[0], vh[1]);
                    mma_f16(o[2 * db2 + 1], ph[kc], vh[2], vh[3]);
                }
            }
        }
    }

    // ---- rowsums: quad-reduce, publish to g_rsum + smem ----
    rs0 += __shfl_xor_sync(0xffffffffu, rs0, 1);
    rs0 += __shfl_xor_sync(0xffffffffu, rs0, 2);
    rs1 += __shfl_xor_sync(0xffffffffu, rs1, 1);
    rs1 += __shfl_xor_sync(0xffffffffu, rs1, 2);
    float* rinv = (float*)(sm + OFF_RINV);
    if (tl == 0) {
        rinv[r0]     = rs0;
        rinv[r0 + 8] = rs1;
        g_rsum[(size_t)bh * S_ + q0 + r0]     = rs0;
        g_rsum[(size_t)bh * S_ + q0 + r0 + 8] = rs1;
    }
    __syncthreads();

    // ---- O write (normalized) ----
    const float ri0 = 1.0f / rinv[r0], ri1 = 1.0f / rinv[r0 + 8];
    #pragma unroll
    for (int df = 0; df < 8; ++df) {
        int colc = 8 * df + 2 * tl;
        *(float2*)(Og + (size_t)r0 * D_ + colc) =
            make_float2(o[df][0] * ri0, o[df][1] * ri0);
        *(float2*)(Og + (size_t)(r0 + 8) * D_ + colc) =
            make_float2(o[df][2] * ri1, o[df][3] * ri1);
    }
}

// ---------- k2: streaming W rescale (one block per row) ----------
__global__ void __launch_bounds__(256, 8)
sdpa_rescale(float* __restrict__ wts)
{
    const int row = blockIdx.x;                 // 0 .. B*H*S-1
    const float ri = 1.0f / g_rsum[row];
    float4* p = (float4*)(wts + (size_t)row * S_);
    const int tid = threadIdx.x;
    #pragma unroll
    for (int i = 0; i < 2; ++i) {
        float4 v = p[tid + 256 * i];
        v.x *= ri; v.y *= ri; v.z *= ri; v.w *= ri;
        p[tid + 256 * i] = v;
    }
}

extern "C" void kernel_launch(void* const* d_in, const int* in_sizes, int n_in,
                              void* d_out, int out_size)
{
    const float* Q    = (const float*)d_in[0];
    const float* K    = (const float*)d_in[1];
    const float* V    = (const float*)d_in[2];
    const int*   mask = (const int*)d_in[3];

    float* out = (float*)d_out;
    float* wts = out + (size_t)B_ * H_ * S_ * D_;

    cudaFuncSetAttribute(sdpa_fused, cudaFuncAttributeMaxDynamicSharedMemorySize, SMEM_SZ);

    dim3 grid(S_ / BM, B_ * H_);
    sdpa_fused<<<grid, NT, SMEM_SZ>>>(Q, K, V, mask, out, wts);
    sdpa_rescale<<<B_ * H_ * S_, 256>>>(wts);
}

// round 12
// speedup vs baseline: 3.2573x; 1.0548x over previous
#include <cuda_runtime.h>
#include <cuda_fp16.h>
#include <cstdint>

// ScaledDotProductAttention B=4,H=16,S=2048,D=64 fp32 + mask [B,1,S,S] int32.
// out [B,H,S,D] then weights [B,H,S,S] concatenated in d_out.
//
// Round 11:
//   k0 (cvt_kv): K,V f32 -> fp16 scratch (once, instead of per-CTA).
//   k1 (sdpa_fused): cp.async double-buffered fp16 K/V tiles; QK=Qh*Kh,
//       PV=Ph*Vh HMMA; exp+mask -> e stored fp16 to g_e scratch; rowsums;
//       O normalized in-kernel.
//   k2 (sdpa_rescale): W = e(fp16) * rinv, streamed (1.6 GB vs 2.15 GB).

#define B_ 4
#define H_ 16
#define S_ 2048
#define D_ 64

constexpr int BM = 128, BN = 128, NT = 256, NTILE = S_ / BN;
constexpr int RB = 144;                    // bytes per fp16 smem row (72 elems)

// double-buffered tile areas
constexpr int OFF_K0   = 0;
constexpr int OFF_V0   = 18432;
constexpr int OFF_K1   = 36864;
constexpr int OFF_V1   = 55296;
constexpr int OFF_RINV = 73728;
constexpr int SMEM_SZ  = OFF_RINV + 512;   // 74240

__device__ float g_rsum[B_ * H_ * S_];
__device__ __align__(16) __half g_Kh[(size_t)B_ * H_ * S_ * D_];
__device__ __align__(16) __half g_Vh[(size_t)B_ * H_ * S_ * D_];
__device__ __align__(16) __half g_e[(size_t)B_ * H_ * S_ * S_];   // 536 MB scratch

// ---------- helpers ----------
__device__ __forceinline__ uint32_t smem_u32(const void* p) {
    uint32_t a;
    asm("{ .reg .u64 t; cvta.to.shared.u64 t, %1; cvt.u32.u64 %0, t; }" : "=r"(a) : "l"(p));
    return a;
}
__device__ __forceinline__ void ldsm4(uint32_t* r, uint32_t a) {
    asm volatile("ldmatrix.sync.aligned.m8n8.x4.shared.b16 {%0,%1,%2,%3}, [%4];"
                 : "=r"(r[0]), "=r"(r[1]), "=r"(r[2]), "=r"(r[3]) : "r"(a));
}
__device__ __forceinline__ void ldsm4t(uint32_t* r, uint32_t a) {
    asm volatile("ldmatrix.sync.aligned.m8n8.x4.trans.shared.b16 {%0,%1,%2,%3}, [%4];"
                 : "=r"(r[0]), "=r"(r[1]), "=r"(r[2]), "=r"(r[3]) : "r"(a));
}
__device__ __forceinline__ void mma_f16(float* c, const uint32_t* a, uint32_t b0, uint32_t b1) {
    asm volatile(
        "mma.sync.aligned.m16n8k16.row.col.f32.f16.f16.f32 "
        "{%0,%1,%2,%3}, {%4,%5,%6,%7}, {%8,%9}, {%0,%1,%2,%3};"
        : "+f"(c[0]), "+f"(c[1]), "+f"(c[2]), "+f"(c[3])
        : "r"(a[0]), "r"(a[1]), "r"(a[2]), "r"(a[3]), "r"(b0), "r"(b1));
}
__device__ __forceinline__ uint32_t pack_h2(float a, float b) {
    __half2 h = __floats2half2_rn(a, b);
    return *(uint32_t*)&h;
}
__device__ __forceinline__ void cp16(uint32_t dst, const void* src) {
    asm volatile("cp.async.cg.shared.global [%0], [%1], 16;" :: "r"(dst), "l"(src));
}
#define CP_COMMIT() asm volatile("cp.async.commit_group;" ::: "memory")
#define CP_WAIT0()  asm volatile("cp.async.wait_group 0;" ::: "memory")

// ---------- k0: K,V f32 -> fp16 scratch ----------
__global__ void __launch_bounds__(256, 8)
cvt_kv(const float* __restrict__ K, const float* __restrict__ V)
{
    int i = blockIdx.x * 256 + threadIdx.x;       // 0 .. B*H*S*D/4-1
    float4 a = ((const float4*)K)[i];
    ((uint2*)g_Kh)[i] = make_uint2(pack_h2(a.x, a.y), pack_h2(a.z, a.w));
    float4 b = ((const float4*)V)[i];
    ((uint2*)g_Vh)[i] = make_uint2(pack_h2(b.x, b.y), pack_h2(b.z, b.w));
}

// ---------- k1: fused QK+exp -> e(fp16) to g_e, PV -> O, rowsums ----------
__global__ void __launch_bounds__(NT, 2)
sdpa_fused(const float* __restrict__ Q, const int* __restrict__ mask,
           float* __restrict__ out)
{
    extern __shared__ char sm[];
    const uint32_t sb = smem_u32(sm);
    const int tid = threadIdx.x, w = tid >> 5, lid = tid & 31;
    const int g = lid >> 2, tl = lid & 3, mi = lid >> 3, l7 = lid & 7;
    const int bh = blockIdx.y, b = bh >> 4, q0 = blockIdx.x * BM;

    const float* Qg = Q + ((size_t)bh * S_ + q0) * D_;
    const char*  KgH = (const char*)(g_Kh + (size_t)bh * S_ * D_);
    const char*  VgH = (const char*)(g_Vh + (size_t)bh * S_ * D_);
    const int*   Mg = mask + (size_t)b * S_ * S_;
    float*       Og = out + ((size_t)bh * S_ + q0) * D_;
    __half*      Eg = g_e + ((size_t)bh * S_ + q0) * S_;

    // prologue: Q (scaled, fp16) -> smem buf K0, hoist Q frags to regs
    for (int idx = tid; idx < BM * 16; idx += NT) {
        int r = idx >> 4, c4 = (idx & 15) * 4;
        float4 v = *(const float4*)(Qg + (size_t)r * D_ + c4);
        *(uint2*)(sm + OFF_K0 + r * RB + c4 * 2) =
            make_uint2(pack_h2(v.x * 0.125f, v.y * 0.125f),
                       pack_h2(v.z * 0.125f, v.w * 0.125f));
    }
    __syncthreads();

    uint32_t aQH[4][4];
    {
        uint32_t arow = (uint32_t)(16 * w + ((mi & 1) << 3) + l7) * RB;
        #pragma unroll
        for (int kc = 0; kc < 4; ++kc)
            ldsm4(aQH[kc], sb + OFF_K0 + arow + kc * 32 + (mi >> 1) * 16);
    }
    __syncthreads();   // Q frags read before cp.async overwrites K0

    const uint32_t offK[2] = {sb + OFF_K0, sb + OFF_K1};
    const uint32_t offV[2] = {sb + OFF_V0, sb + OFF_V1};

    // issue tile 0
    {
        const char* ks = KgH;          // tile 0
        const char* vs = VgH;
        #pragma unroll
        for (int j = 0; j < 4; ++j) {
            int c = tid + 256 * j, row = c >> 3, cc = c & 7;
            cp16(offK[0] + row * RB + cc * 16, ks + row * 128 + cc * 16);
            cp16(offV[0] + row * RB + cc * 16, vs + row * 128 + cc * 16);
        }
        CP_COMMIT();
    }

    const int r0 = 16 * w + g;
    const int* m0p = Mg + (size_t)(q0 + r0) * S_;
    const int* m1p = Mg + (size_t)(q0 + r0 + 8) * S_;
    __half* e0p = Eg + (size_t)r0 * S_;
    __half* e1p = Eg + (size_t)(r0 + 8) * S_;

    float rs0 = 0.f, rs1 = 0.f;
    float o[8][4];
    #pragma unroll
    for (int df = 0; df < 8; ++df)
        #pragma unroll
        for (int i = 0; i < 4; ++i) o[df][i] = 0.f;

    for (int t = 0; t < NTILE; ++t) {
        CP_WAIT0();
        __syncthreads();    // tile t ready; prev compute done (buffer reuse safe)

        if (t + 1 < NTILE) {
            const char* ks = KgH + (size_t)(t + 1) * BN * D_ * 2;
            const char* vs = VgH + (size_t)(t + 1) * BN * D_ * 2;
            const uint32_t dK = offK[(t + 1) & 1], dV = offV[(t + 1) & 1];
            #pragma unroll
            for (int j = 0; j < 4; ++j) {
                int c = tid + 256 * j, row = c >> 3, cc = c & 7;
                cp16(dK + row * RB + cc * 16, ks + row * 128 + cc * 16);
                cp16(dV + row * RB + cc * 16, vs + row * 128 + cc * 16);
            }
            CP_COMMIT();
        }

        const uint32_t bK = offK[t & 1], bV = offV[t & 1];

        #pragma unroll
        for (int ch2 = 0; ch2 < 2; ++ch2) {
            const int co = 64 * ch2;
            const int colb = t * BN + co;

            // hoist mask loads: in flight during QK MMAs
            int2 mA[8], mB[8];
            #pragma unroll
            for (int nf = 0; nf < 8; ++nf) {
                int col = colb + 8 * nf + 2 * tl;
                mA[nf] = *(const int2*)(m0p + col);
                mB[nf] = *(const int2*)(m1p + col);
            }

            // QK scores: Qh * Kh
            float c[8][4];
            #pragma unroll
            for (int nf = 0; nf < 8; ++nf)
                #pragma unroll
                for (int i = 0; i < 4; ++i) c[nf][i] = 0.f;
            #pragma unroll
            for (int kc = 0; kc < 4; ++kc) {
                const uint32_t bcol = kc * 32 + (mi & 1) * 16;
                #pragma unroll
                for (int nf2 = 0; nf2 < 4; ++nf2) {
                    uint32_t bH[4];
                    uint32_t brow = (uint32_t)(co + nf2 * 16 + ((mi >> 1) << 3) + l7) * RB;
                    ldsm4(bH, bK + brow + bcol);
                    mma_f16(c[2 * nf2],     aQH[kc], bH[0], bH[1]);
                    mma_f16(c[2 * nf2 + 1], aQH[kc], bH[2], bH[3]);
                }
            }

            // exp + mask; e -> fp16 (store to g_e + keep as PV A-frags); rowsums
            uint32_t ph[4][4];
            #pragma unroll
            for (int nf = 0; nf < 8; ++nf) {
                int col = colb + 8 * nf + 2 * tl;
                float e0 = mA[nf].x ? __expf(c[nf][0]) : 0.f;
                float e1 = mA[nf].y ? __expf(c[nf][1]) : 0.f;
                float e2 = mB[nf].x ? __expf(c[nf][2]) : 0.f;
                float e3 = mB[nf].y ? __expf(c[nf][3]) : 0.f;
                uint32_t p01 = pack_h2(e0, e1);
                uint32_t p23 = pack_h2(e2, e3);
                *(uint32_t*)(e0p + col) = p01;
                *(uint32_t*)(e1p + col) = p23;
                rs0 += e0 + e1;
                rs1 += e2 + e3;
                ph[nf >> 1][((nf & 1) << 1) | 0] = p01;
                ph[nf >> 1][((nf & 1) << 1) | 1] = p23;
            }

            // PV: O += Ph * Vh
            #pragma unroll
            for (int kc = 0; kc < 4; ++kc) {
                uint32_t vrow = (uint32_t)(co + kc * 16 + ((mi & 1) << 3) + l7) * RB;
                #pragma unroll
                for (int db2 = 0; db2 < 4; ++db2) {
                    uint32_t vh[4];
                    ldsm4t(vh, bV + vrow + db2 * 32 + (mi >> 1) * 16);
                    mma_f16(o[2 * db2],     ph[kc], vh[0], vh[1]);
                    mma_f16(o[2 * db2 + 1], ph[kc], vh[2], vh[3]);
                }
            }
        }
    }

    // ---- rowsums: quad-reduce, publish to g_rsum + smem ----
    rs0 += __shfl_xor_sync(0xffffffffu, rs0, 1);
    rs0 += __shfl_xor_sync(0xffffffffu, rs0, 2);
    rs1 += __shfl_xor_sync(0xffffffffu, rs1, 1);
    rs1 += __shfl_xor_sync(0xffffffffu, rs1, 2);
    float* rinv = (float*)(sm + OFF_RINV);
    if (tl == 0) {
        rinv[r0]     = rs0;
        rinv[r0 + 8] = rs1;
        g_rsum[(size_t)bh * S_ + q0 + r0]     = rs0;
        g_rsum[(size_t)bh * S_ + q0 + r0 + 8] = rs1;
    }
    __syncthreads();

    // ---- O write (normalized) ----
    const float ri0 = 1.0f / rinv[r0], ri1 = 1.0f / rinv[r0 + 8];
    #pragma unroll
    for (int df = 0; df < 8; ++df) {
        int colc = 8 * df + 2 * tl;
        *(float2*)(Og + (size_t)r0 * D_ + colc) =
            make_float2(o[df][0] * ri0, o[df][1] * ri0);
        *(float2*)(Og + (size_t)(r0 + 8) * D_ + colc) =
            make_float2(o[df][2] * ri1, o[df][3] * ri1);
    }
}

// ---------- k2: W = e(fp16) * rinv (one block per row) ----------
__global__ void __launch_bounds__(256, 8)
sdpa_rescale(float* __restrict__ wts)
{
    const int row = blockIdx.x;                 // 0 .. B*H*S-1
    const float ri = 1.0f / g_rsum[row];
    const int tid = threadIdx.x;

    const uint4 ev = ((const uint4*)(g_e + (size_t)row * S_))[tid];
    float2 f0 = __half22float2(*(const __half2*)&ev.x);
    float2 f1 = __half22float2(*(const __half2*)&ev.y);
    float2 f2 = __half22float2(*(const __half2*)&ev.z);
    float2 f3 = __half22float2(*(const __half2*)&ev.w);

    float4* p = (float4*)(wts + (size_t)row * S_ + 8 * tid);
    p[0] = make_float4(f0.x * ri, f0.y * ri, f1.x * ri, f1.y * ri);
    p[1] = make_float4(f2.x * ri, f2.y * ri, f3.x * ri, f3.y * ri);
}

extern "C" void kernel_launch(void* const* d_in, const int* in_sizes, int n_in,
                              void* d_out, int out_size)
{
    const float* Q    = (const float*)d_in[0];
    const float* K    = (const float*)d_in[1];
    const float* V    = (const float*)d_in[2];
    const int*   mask = (const int*)d_in[3];

    float* out = (float*)d_out;
    float* wts = out + (size_t)B_ * H_ * S_ * D_;

    cudaFuncSetAttribute(sdpa_fused, cudaFuncAttributeMaxDynamicSharedMemorySize, SMEM_SZ);

    cvt_kv<<<(B_ * H_ * S_ * D_ / 4) / 256, 256>>>(K, V);
    dim3 grid(S_ / BM, B_ * H_);
    sdpa_fused<<<grid, NT, SMEM_SZ>>>(Q, mask, out);
    sdpa_rescale<<<B_ * H_ * S_, 256>>>(wts);
}

// round 13
// speedup vs baseline: 3.8729x; 1.1890x over previous
#include <cuda_runtime.h>
#include <cuda_fp16.h>
#include <cstdint>

// ScaledDotProductAttention B=4,H=16,S=2048,D=64 fp32 + mask [B,1,S,S] int32.
// out [B,H,S,D] then weights [B,H,S,S] concatenated in d_out.
//
// Round 12:
//   k0a (cvt_kv):   K,V f32 -> fp16 scratch.
//   k0b (cvt_mask): mask int32 -> fp16 {0,1} scratch.
//   k1  (sdpa_fused): cp.async double-buffered fp16 K/V; QK=Qh*Kh HMMA;
//        exp -> pack -> HMUL2 mask -> e(fp16) to g_e + PV A-frags;
//        PV=Ph*Vh -> RAW (unnormalized) O. No rowsums, no epilogue math.
//   k2  (sdpa_norm): per row: read e(fp16), block-reduce rsum, write
//        W = e*rinv (f32) and normalize the row's 64-float O slice.

#define B_ 4
#define H_ 16
#define S_ 2048
#define D_ 64

constexpr int BM = 128, BN = 128, NT = 256, NTILE = S_ / BN;
constexpr int RB = 144;                    // bytes per fp16 smem row (72 elems)

// double-buffered tile areas
constexpr int OFF_K0  = 0;
constexpr int OFF_V0  = 18432;
constexpr int OFF_K1  = 36864;
constexpr int OFF_V1  = 55296;
constexpr int SMEM_SZ = 73728;

__device__ __align__(16) __half g_Kh[(size_t)B_ * H_ * S_ * D_];
__device__ __align__(16) __half g_Vh[(size_t)B_ * H_ * S_ * D_];
__device__ __align__(16) __half g_Mh[(size_t)B_ * S_ * S_];        // fp16 {0,1}
__device__ __align__(16) __half g_e[(size_t)B_ * H_ * S_ * S_];    // 536 MB scratch

// ---------- helpers ----------
__device__ __forceinline__ uint32_t smem_u32(const void* p) {
    uint32_t a;
    asm("{ .reg .u64 t; cvta.to.shared.u64 t, %1; cvt.u32.u64 %0, t; }" : "=r"(a) : "l"(p));
    return a;
}
__device__ __forceinline__ void ldsm4(uint32_t* r, uint32_t a) {
    asm volatile("ldmatrix.sync.aligned.m8n8.x4.shared.b16 {%0,%1,%2,%3}, [%4];"
                 : "=r"(r[0]), "=r"(r[1]), "=r"(r[2]), "=r"(r[3]) : "r"(a));
}
__device__ __forceinline__ void ldsm4t(uint32_t* r, uint32_t a) {
    asm volatile("ldmatrix.sync.aligned.m8n8.x4.trans.shared.b16 {%0,%1,%2,%3}, [%4];"
                 : "=r"(r[0]), "=r"(r[1]), "=r"(r[2]), "=r"(r[3]) : "r"(a));
}
__device__ __forceinline__ void mma_f16(float* c, const uint32_t* a, uint32_t b0, uint32_t b1) {
    asm volatile(
        "mma.sync.aligned.m16n8k16.row.col.f32.f16.f16.f32 "
        "{%0,%1,%2,%3}, {%4,%5,%6,%7}, {%8,%9}, {%0,%1,%2,%3};"
        : "+f"(c[0]), "+f"(c[1]), "+f"(c[2]), "+f"(c[3])
        : "r"(a[0]), "r"(a[1]), "r"(a[2]), "r"(a[3]), "r"(b0), "r"(b1));
}
__device__ __forceinline__ uint32_t pack_h2(float a, float b) {
    __half2 h = __floats2half2_rn(a, b);
    return *(uint32_t*)&h;
}
__device__ __forceinline__ uint32_t mul2(uint32_t a, uint32_t b) {
    __half2 r = __hmul2(*(__half2*)&a, *(__half2*)&b);
    return *(uint32_t*)&r;
}
__device__ __forceinline__ void cp16(uint32_t dst, const void* src) {
    asm volatile("cp.async.cg.shared.global [%0], [%1], 16;" :: "r"(dst), "l"(src));
}
#define CP_COMMIT() asm volatile("cp.async.commit_group;" ::: "memory")
#define CP_WAIT0()  asm volatile("cp.async.wait_group 0;" ::: "memory")

// ---------- k0a: K,V f32 -> fp16 scratch ----------
__global__ void __launch_bounds__(256, 8)
cvt_kv(const float* __restrict__ K, const float* __restrict__ V)
{
    int i = blockIdx.x * 256 + threadIdx.x;       // 0 .. B*H*S*D/4-1
    float4 a = ((const float4*)K)[i];
    ((uint2*)g_Kh)[i] = make_uint2(pack_h2(a.x, a.y), pack_h2(a.z, a.w));
    float4 b = ((const float4*)V)[i];
    ((uint2*)g_Vh)[i] = make_uint2(pack_h2(b.x, b.y), pack_h2(b.z, b.w));
}

// ---------- k0b: mask int32 -> fp16 {0,1} ----------
__global__ void __launch_bounds__(256, 8)
cvt_mask(const int* __restrict__ mask)
{
    int i = blockIdx.x * 256 + threadIdx.x;       // 0 .. B*S*S/4-1
    int4 m = ((const int4*)mask)[i];
    ((uint2*)g_Mh)[i] = make_uint2(pack_h2((float)m.x, (float)m.y),
                                   pack_h2((float)m.z, (float)m.w));
}

// ---------- k1: QK+exp+mask -> e(fp16) to g_e, PV -> raw O ----------
__global__ void __launch_bounds__(NT, 2)
sdpa_fused(const float* __restrict__ Q, float* __restrict__ out)
{
    extern __shared__ char sm[];
    const uint32_t sb = smem_u32(sm);
    const int tid = threadIdx.x, w = tid >> 5, lid = tid & 31;
    const int g = lid >> 2, tl = lid & 3, mi = lid >> 3, l7 = lid & 7;
    const int bh = blockIdx.y, b = bh >> 4, q0 = blockIdx.x * BM;

    const float* Qg  = Q + ((size_t)bh * S_ + q0) * D_;
    const char*  KgH = (const char*)(g_Kh + (size_t)bh * S_ * D_);
    const char*  VgH = (const char*)(g_Vh + (size_t)bh * S_ * D_);
    const __half* Mh = g_Mh + (size_t)b * S_ * S_;
    float*       Og  = out + ((size_t)bh * S_ + q0) * D_;
    __half*      Eg  = g_e + ((size_t)bh * S_ + q0) * S_;

    // prologue: Q (scaled, fp16) -> smem buf K0, hoist Q frags to regs
    for (int idx = tid; idx < BM * 16; idx += NT) {
        int r = idx >> 4, c4 = (idx & 15) * 4;
        float4 v = *(const float4*)(Qg + (size_t)r * D_ + c4);
        *(uint2*)(sm + OFF_K0 + r * RB + c4 * 2) =
            make_uint2(pack_h2(v.x * 0.125f, v.y * 0.125f),
                       pack_h2(v.z * 0.125f, v.w * 0.125f));
    }
    __syncthreads();

    uint32_t aQH[4][4];
    {
        uint32_t arow = (uint32_t)(16 * w + ((mi & 1) << 3) + l7) * RB;
        #pragma unroll
        for (int kc = 0; kc < 4; ++kc)
            ldsm4(aQH[kc], sb + OFF_K0 + arow + kc * 32 + (mi >> 1) * 16);
    }
    __syncthreads();   // Q frags read before cp.async overwrites K0

    const uint32_t offK[2] = {sb + OFF_K0, sb + OFF_K1};
    const uint32_t offV[2] = {sb + OFF_V0, sb + OFF_V1};

    // issue tile 0
    {
        #pragma unroll
        for (int j = 0; j < 4; ++j) {
            int c = tid + 256 * j, row = c >> 3, cc = c & 7;
            cp16(offK[0] + row * RB + cc * 16, KgH + row * 128 + cc * 16);
            cp16(offV[0] + row * RB + cc * 16, VgH + row * 128 + cc * 16);
        }
        CP_COMMIT();
    }

    const int r0 = 16 * w + g;
    const __half* m0p = Mh + (size_t)(q0 + r0) * S_;
    const __half* m1p = Mh + (size_t)(q0 + r0 + 8) * S_;
    __half* e0p = Eg + (size_t)r0 * S_;
    __half* e1p = Eg + (size_t)(r0 + 8) * S_;

    float o[8][4];
    #pragma unroll
    for (int df = 0; df < 8; ++df)
        #pragma unroll
        for (int i = 0; i < 4; ++i) o[df][i] = 0.f;

    for (int t = 0; t < NTILE; ++t) {
        CP_WAIT0();
        __syncthreads();    // tile t ready; prev compute done (buffer reuse safe)

        if (t + 1 < NTILE) {
            const char* ks = KgH + (size_t)(t + 1) * BN * D_ * 2;
            const char* vs = VgH + (size_t)(t + 1) * BN * D_ * 2;
            const uint32_t dK = offK[(t + 1) & 1], dV = offV[(t + 1) & 1];
            #pragma unroll
            for (int j = 0; j < 4; ++j) {
                int c = tid + 256 * j, row = c >> 3, cc = c & 7;
                cp16(dK + row * RB + cc * 16, ks + row * 128 + cc * 16);
                cp16(dV + row * RB + cc * 16, vs + row * 128 + cc * 16);
            }
            CP_COMMIT();
        }

        const uint32_t bK = offK[t & 1], bV = offV[t & 1];

        #pragma unroll
        for (int ch2 = 0; ch2 < 2; ++ch2) {
            const int co = 64 * ch2;
            const int colb = t * BN + co;

            // hoist mask loads (fp16 pairs): in flight during QK MMAs
            uint32_t mA[8], mB[8];
            #pragma unroll
            for (int nf = 0; nf < 8; ++nf) {
                int col = colb + 8 * nf + 2 * tl;
                mA[nf] = *(const uint32_t*)(m0p + col);
                mB[nf] = *(const uint32_t*)(m1p + col);
            }

            // QK scores: Qh * Kh
            float c[8][4];
            #pragma unroll
            for (int nf = 0; nf < 8; ++nf)
                #pragma unroll
                for (int i = 0; i < 4; ++i) c[nf][i] = 0.f;
            #pragma unroll
            for (int kc = 0; kc < 4; ++kc) {
                const uint32_t bcol = kc * 32 + (mi & 1) * 16;
                #pragma unroll
                for (int nf2 = 0; nf2 < 4; ++nf2) {
                    uint32_t bH[4];
                    uint32_t brow = (uint32_t)(co + nf2 * 16 + ((mi >> 1) << 3) + l7) * RB;
                    ldsm4(bH, bK + brow + bcol);
                    mma_f16(c[2 * nf2],     aQH[kc], bH[0], bH[1]);
                    mma_f16(c[2 * nf2 + 1], aQH[kc], bH[2], bH[3]);
                }
            }

            // exp -> pack fp16 -> mask multiply -> store + PV A-frags
            uint32_t ph[4][4];
            #pragma unroll
            for (int nf = 0; nf < 8; ++nf) {
                int col = colb + 8 * nf + 2 * tl;
                float e0 = __expf(c[nf][0]);
                float e1 = __expf(c[nf][1]);
                float e2 = __expf(c[nf][2]);
                float e3 = __expf(c[nf][3]);
                uint32_t p01 = mul2(pack_h2(e0, e1), mA[nf]);
                uint32_t p23 = mul2(pack_h2(e2, e3), mB[nf]);
                *(uint32_t*)(e0p + col) = p01;
                *(uint32_t*)(e1p + col) = p23;
                ph[nf >> 1][((nf & 1) << 1) | 0] = p01;
                ph[nf >> 1][((nf & 1) << 1) | 1] = p23;
            }

            // PV: O += Ph * Vh
            #pragma unroll
            for (int kc = 0; kc < 4; ++kc) {
                uint32_t vrow = (uint32_t)(co + kc * 16 + ((mi & 1) << 3) + l7) * RB;
                #pragma unroll
                for (int db2 = 0; db2 < 4; ++db2) {
                    uint32_t vh[4];
                    ldsm4t(vh, bV + vrow + db2 * 32 + (mi >> 1) * 16);
                    mma_f16(o[2 * db2],     ph[kc], vh[0], vh[1]);
                    mma_f16(o[2 * db2 + 1], ph[kc], vh[2], vh[3]);
                }
            }
        }
    }

    // ---- O write (RAW, normalized later by k2) ----
    #pragma unroll
    for (int df = 0; df < 8; ++df) {
        int colc = 8 * df + 2 * tl;
        *(float2*)(Og + (size_t)r0 * D_ + colc) =
            make_float2(o[df][0], o[df][1]);
        *(float2*)(Og + (size_t)(r0 + 8) * D_ + colc) =
            make_float2(o[df][2], o[df][3]);
    }
}

// ---------- k2: per-row rowsum + W = e*rinv + O normalize ----------
__global__ void __launch_bounds__(256, 8)
sdpa_norm(float* __restrict__ out, float* __restrict__ wts)
{
    const int row = blockIdx.x;                 // 0 .. B*H*S-1
    const int tid = threadIdx.x;
    __shared__ float red[8];
    __shared__ float s_rinv;

    const uint4 ev = ((const uint4*)(g_e + (size_t)row * S_))[tid];
    float2 f0 = __half22float2(*(const __half2*)&ev.x);
    float2 f1 = __half22float2(*(const __half2*)&ev.y);
    float2 f2 = __half22float2(*(const __half2*)&ev.z);
    float2 f3 = __half22float2(*(const __half2*)&ev.w);

    float s = (f0.x + f0.y) + (f1.x + f1.y) + (f2.x + f2.y) + (f3.x + f3.y);
    #pragma unroll
    for (int off = 16; off > 0; off >>= 1)
        s += __shfl_xor_sync(0xffffffffu, s, off);
    if ((tid & 31) == 0) red[tid >> 5] = s;
    __syncthreads();
    if (tid == 0) {
        float t = 0.f;
        #pragma unroll
        for (int i = 0; i < 8; ++i) t += red[i];
        s_rinv = 1.0f / t;
    }
    __syncthreads();
    const float ri = s_rinv;

    float4* p = (float4*)(wts + (size_t)row * S_ + 8 * tid);
    p[0] = make_float4(f0.x * ri, f0.y * ri, f1.x * ri, f1.y * ri);
    p[1] = make_float4(f2.x * ri, f2.y * ri, f3.x * ri, f3.y * ri);

    if (tid < 16) {
        float4* op = (float4*)(out + (size_t)row * D_) + tid;
        float4 ov = *op;
        ov.x *= ri; ov.y *= ri; ov.z *= ri; ov.w *= ri;
        *op = ov;
    }
}

extern "C" void kernel_launch(void* const* d_in, const int* in_sizes, int n_in,
                              void* d_out, int out_size)
{
    const float* Q    = (const float*)d_in[0];
    const float* K    = (const float*)d_in[1];
    const float* V    = (const float*)d_in[2];
    const int*   mask = (const int*)d_in[3];

    float* out = (float*)d_out;
    float* wts = out + (size_t)B_ * H_ * S_ * D_;

    cudaFuncSetAttribute(sdpa_fused, cudaFuncAttributeMaxDynamicSharedMemorySize, SMEM_SZ);

    cvt_kv<<<(B_ * H_ * S_ * D_ / 4) / 256, 256>>>(K, V);
    cvt_mask<<<(B_ * S_ * S_ / 4) / 256, 256>>>(mask);
    dim3 grid(S_ / BM, B_ * H_);
    sdpa_fused<<<grid, NT, SMEM_SZ>>>(Q, out);
    sdpa_norm<<<B_ * H_ * S_, 256>>>(out, wts);
}